// round 3
// baseline (speedup 1.0000x reference)
#include <cuda_runtime.h>
#include <cuda_bf16.h>
#include <math.h>

// ---------------------------------------------------------------------------
// MLA attention pipeline, fp32. B=4, T=2048, D=512, H=8, KVH=2, HD=64
// Round 3: flash attention retiled to BM=128 x BN=64 (0.67 FMA/byte LDS),
// heavy-first causal block ordering, dynamic 80KB smem.
// ---------------------------------------------------------------------------

#define Bb   4
#define Tt   2048
#define Dd   512
#define Hh   8
#define KVHh 2
#define HDd  64
#define BT   (Bb*Tt)      // 8192
#define EPSF 1e-6f

// ------------------------- scratch (device globals) ------------------------
__device__ float g_cq  [BT*256];
__device__ float g_qn  [BT*256];
__device__ float g_qr  [BT*256];
__device__ float g_ckv [BT*128];
__device__ float g_kn  [BT*64];
__device__ float g_kr  [BT*64];
__device__ float g_vraw[BT*128];
__device__ float g_vres[BT*512];
__device__ float g_q   [BT*512];              // [B,H,T,HD]
__device__ float g_k   [Bb*KVHh*Tt*HDd];      // [B,KVH,T,HD]
__device__ float g_v   [Bb*KVHh*Tt*HDd];      // [B,KVH,T,HD]
__device__ float g_ao  [BT*512];              // attn_out + v_res, [B*T, H*HD]

// ---------------------------------------------------------------------------
// SGEMM 64x64 tile (N%64 cases). Requires M%64==0, N%64==0, K%16==0.
// ---------------------------------------------------------------------------
__global__ __launch_bounds__(256) void sgemm64(
    const float* __restrict__ A, const float* __restrict__ B,
    float* __restrict__ C, int M, int N, int K)
{
    __shared__ float As[16][64];
    __shared__ float Bs[16][64];

    const int bm = blockIdx.y * 64;
    const int bn = blockIdx.x * 64;
    const int tid = threadIdx.x;
    const int ty = tid >> 4, tx = tid & 15;
    const int am = tid >> 2, ak4 = tid & 3;
    const int bk = tid >> 4, bn4 = tid & 15;

    float acc[4][4] = {};

    for (int k0 = 0; k0 < K; k0 += 16) {
        float4 av = *(const float4*)(A + (size_t)(bm + am) * K + k0 + ak4 * 4);
        float4 bv = *(const float4*)(B + (size_t)(k0 + bk) * N + bn + bn4 * 4);
        __syncthreads();
        As[ak4 * 4 + 0][am] = av.x;
        As[ak4 * 4 + 1][am] = av.y;
        As[ak4 * 4 + 2][am] = av.z;
        As[ak4 * 4 + 3][am] = av.w;
        *(float4*)&Bs[bk][bn4 * 4] = bv;
        __syncthreads();
        #pragma unroll
        for (int kk = 0; kk < 16; ++kk) {
            float4 a = *(const float4*)&As[kk][ty * 4];
            float4 b = *(const float4*)&Bs[kk][tx * 4];
            acc[0][0] += a.x * b.x; acc[0][1] += a.x * b.y; acc[0][2] += a.x * b.z; acc[0][3] += a.x * b.w;
            acc[1][0] += a.y * b.x; acc[1][1] += a.y * b.y; acc[1][2] += a.y * b.z; acc[1][3] += a.y * b.w;
            acc[2][0] += a.z * b.x; acc[2][1] += a.z * b.y; acc[2][2] += a.z * b.z; acc[2][3] += a.z * b.w;
            acc[3][0] += a.w * b.x; acc[3][1] += a.w * b.y; acc[3][2] += a.w * b.z; acc[3][3] += a.w * b.w;
        }
    }

    #pragma unroll
    for (int i = 0; i < 4; ++i) {
        float4 o = make_float4(acc[i][0], acc[i][1], acc[i][2], acc[i][3]);
        *(float4*)(C + (size_t)(bm + ty * 4 + i) * N + bn + tx * 4) = o;
    }
}

// ---------------------------------------------------------------------------
// SGEMM 128x128 tile, BK=8, 256 threads, 2x2 blocks of 4x4 microtiles.
// ---------------------------------------------------------------------------
__global__ __launch_bounds__(256) void sgemm128(
    const float* __restrict__ A, const float* __restrict__ B,
    float* __restrict__ C, int M, int N, int K)
{
    __shared__ float As[8][128];
    __shared__ float Bs[8][128];

    const int bm = blockIdx.y * 128;
    const int bn = blockIdx.x * 128;
    const int tid = threadIdx.x;
    const int ty = tid >> 4, tx = tid & 15;
    const int arow = tid >> 1, ak = (tid & 1) * 4;
    const int bk = tid >> 5, bcol = (tid & 31) * 4;

    float acc[2][2][4][4] = {};

    for (int k0 = 0; k0 < K; k0 += 8) {
        float4 av = *(const float4*)(A + (size_t)(bm + arow) * K + k0 + ak);
        float4 bv = *(const float4*)(B + (size_t)(k0 + bk) * N + bn + bcol);
        __syncthreads();
        As[ak + 0][arow] = av.x;
        As[ak + 1][arow] = av.y;
        As[ak + 2][arow] = av.z;
        As[ak + 3][arow] = av.w;
        *(float4*)&Bs[bk][bcol] = bv;
        __syncthreads();
        #pragma unroll
        for (int kk = 0; kk < 8; ++kk) {
            float4 a0 = *(const float4*)&As[kk][ty * 4];
            float4 a1 = *(const float4*)&As[kk][64 + ty * 4];
            float4 b0 = *(const float4*)&Bs[kk][tx * 4];
            float4 b1 = *(const float4*)&Bs[kk][64 + tx * 4];
            #pragma unroll
            for (int ri = 0; ri < 2; ++ri) {
                float4 a = ri ? a1 : a0;
                #pragma unroll
                for (int ci = 0; ci < 2; ++ci) {
                    float4 b = ci ? b1 : b0;
                    acc[ri][ci][0][0] += a.x * b.x; acc[ri][ci][0][1] += a.x * b.y;
                    acc[ri][ci][0][2] += a.x * b.z; acc[ri][ci][0][3] += a.x * b.w;
                    acc[ri][ci][1][0] += a.y * b.x; acc[ri][ci][1][1] += a.y * b.y;
                    acc[ri][ci][1][2] += a.y * b.z; acc[ri][ci][1][3] += a.y * b.w;
                    acc[ri][ci][2][0] += a.z * b.x; acc[ri][ci][2][1] += a.z * b.y;
                    acc[ri][ci][2][2] += a.z * b.z; acc[ri][ci][2][3] += a.z * b.w;
                    acc[ri][ci][3][0] += a.w * b.x; acc[ri][ci][3][1] += a.w * b.y;
                    acc[ri][ci][3][2] += a.w * b.z; acc[ri][ci][3][3] += a.w * b.w;
                }
            }
        }
    }

    #pragma unroll
    for (int ri = 0; ri < 2; ++ri)
        #pragma unroll
        for (int i = 0; i < 4; ++i) {
            size_t row = (size_t)(bm + ri * 64 + ty * 4 + i);
            #pragma unroll
            for (int ci = 0; ci < 2; ++ci) {
                float4 o = make_float4(acc[ri][ci][i][0], acc[ri][ci][i][1],
                                       acc[ri][ci][i][2], acc[ri][ci][i][3]);
                *(float4*)(C + row * N + bn + ci * 64 + tx * 4) = o;
            }
        }
}

// ---------------------------------------------------------------------------
// In-place RMSNorm over rows of length `dim`. 1 block per row.
// ---------------------------------------------------------------------------
__global__ __launch_bounds__(128) void rms_inplace(
    float* __restrict__ x, const float* __restrict__ w, int dim)
{
    const int row = blockIdx.x;
    float* xr = x + (size_t)row * dim;
    float ss = 0.f;
    for (int i = threadIdx.x; i < dim; i += 128) { float v = xr[i]; ss += v * v; }
    #pragma unroll
    for (int off = 16; off; off >>= 1) ss += __shfl_xor_sync(0xffffffffu, ss, off);
    __shared__ float sred[4];
    if ((threadIdx.x & 31) == 0) sred[threadIdx.x >> 5] = ss;
    __syncthreads();
    float tot = sred[0] + sred[1] + sred[2] + sred[3];
    float rr = rsqrtf(tot / (float)dim + EPSF);
    for (int i = threadIdx.x; i < dim; i += 128) xr[i] = xr[i] * rr * w[i];
}

// ---------------------------------------------------------------------------
// Assemble: RoPE + concat + per-head RMSNorm + layout to [B,h,T,64].
// ---------------------------------------------------------------------------
__global__ __launch_bounds__(256) void assemble(
    const float* __restrict__ qn, const float* __restrict__ qr,
    const float* __restrict__ kn, const float* __restrict__ kr,
    const float* __restrict__ vraw,
    const float* __restrict__ qhw, const float* __restrict__ khw,
    float* __restrict__ q, float* __restrict__ k, float* __restrict__ v)
{
    const int t = blockIdx.x, b = blockIdx.y;
    const int row = b * Tt + t;
    const int w = threadIdx.x >> 5, lane = threadIdx.x & 31;

    const int fi = lane & 15;
    float invf = (float)exp(-((double)fi / 16.0) * log(500000.0));
    float ph = (float)t * invf;
    float sv, cv;
    sincosf(ph, &sv, &cv);

    // ---- Q heads: warp w handles head h = w ----
    {
        const int h = w;
        const float* qnr = qn + (size_t)row * 256 + h * 32;
        const float* qrr = qr + (size_t)row * 256 + h * 32;
        float v0 = qnr[lane];
        float x1 = qrr[lane];
        float xr_ = (lane < 16) ? -qrr[lane + 16] : qrr[lane - 16];
        float v1 = x1 * cv + xr_ * sv;
        float ss = v0 * v0 + v1 * v1;
        #pragma unroll
        for (int off = 16; off; off >>= 1) ss += __shfl_xor_sync(0xffffffffu, ss, off);
        float rr = rsqrtf(ss / 64.0f + EPSF);
        float* qo = q + ((size_t)(b * Hh + h) * Tt + t) * 64;
        qo[lane]      = v0 * rr * qhw[lane];
        qo[lane + 32] = v1 * rr * qhw[lane + 32];
    }

    // ---- K heads ----
    if (w < KVHh) {
        const int kvh = w;
        const float* knr = kn + (size_t)row * 64 + kvh * 32;
        const float* krr = kr + (size_t)row * 64 + kvh * 32;
        float v0 = knr[lane];
        float x1 = krr[lane];
        float xr_ = (lane < 16) ? -krr[lane + 16] : krr[lane - 16];
        float v1 = x1 * cv + xr_ * sv;
        float ss = v0 * v0 + v1 * v1;
        #pragma unroll
        for (int off = 16; off; off >>= 1) ss += __shfl_xor_sync(0xffffffffu, ss, off);
        float rr = rsqrtf(ss / 64.0f + EPSF);
        float* ko = k + ((size_t)(b * KVHh + kvh) * Tt + t) * 64;
        ko[lane]      = v0 * rr * khw[lane];
        ko[lane + 32] = v1 * rr * khw[lane + 32];
    }

    // ---- V reshape ----
    for (int i = threadIdx.x; i < 128; i += 256) {
        int kvh = i >> 6, d = i & 63;
        v[((size_t)(b * KVHh + kvh) * Tt + t) * 64 + d] = vraw[(size_t)row * 128 + i];
    }
}

// ---------------------------------------------------------------------------
// Fused causal flash attention, fp32. BM=128, BN=64, 256 threads.
// Grid (T/128, H, B); blockIdx.x maps heavy-first: qt = nQT-1-blockIdx.x.
// Dynamic smem 80KB: Qs[64][128] swz, KP[64][128] (K as [64][64] swz then
// overlaid by P), Vs[64][64] natural. Per-thread 8x4 microtiles (split-64).
// ---------------------------------------------------------------------------
__device__ __forceinline__ int swz64(int maj, int mnr) {
    return (maj << 6) + ((((mnr >> 2) ^ (maj & 15)) << 2) | (mnr & 3));
}
__device__ __forceinline__ int swz128(int maj, int mnr) {
    return (maj << 7) + ((((mnr >> 2) ^ (maj & 31)) << 2) | (mnr & 3));
}

__global__ __launch_bounds__(256) void flash128(
    const float* __restrict__ Q, const float* __restrict__ Kk,
    const float* __restrict__ V, const float* __restrict__ vres,
    float* __restrict__ out)
{
    extern __shared__ float sm[];
    float* Qs  = sm;              // 64*128
    float* KPs = sm + 64 * 128;   // 64*128 (K in first 64*64 as swz64)
    float* Vs  = sm + 2 * 64 * 128; // 64*64

    const int qt = (Tt / 128 - 1) - blockIdx.x;   // heavy blocks first
    const int h = blockIdx.y, b = blockIdx.z;
    const int kvh = h >> 2;   // H/KVH = 4
    const float* qb = Q  + (((size_t)b * Hh   + h)   * Tt + qt * 128) * 64;
    const float* kb = Kk + (((size_t)b * KVHh + kvh) * Tt) * 64;
    const float* vb = V  + (((size_t)b * KVHh + kvh) * Tt) * 64;

    const int tid = threadIdx.x;
    const int ty = tid >> 4, tx = tid & 15;
    const int m0 = ty * 4;          // rows m0..m0+3 and m0+64..m0+67
    const int n0 = tx * 4;

    // load Q tile (pre-scaled), transposed+swizzled: Qs[d][m]
    #pragma unroll
    for (int j = 0; j < 8; ++j) {
        int job = tid + j * 256;          // 0..2047
        int row = job >> 4, d4 = job & 15, dd = d4 * 4;
        float4 val = *(const float4*)(qb + row * 64 + d4 * 4);
        Qs[swz128(dd + 0, row)] = val.x * 0.125f;
        Qs[swz128(dd + 1, row)] = val.y * 0.125f;
        Qs[swz128(dd + 2, row)] = val.z * 0.125f;
        Qs[swz128(dd + 3, row)] = val.w * 0.125f;
    }

    float O[2][4][4] = {};
    float mI[2][4] = {{-3.0e38f,-3.0e38f,-3.0e38f,-3.0e38f},
                      {-3.0e38f,-3.0e38f,-3.0e38f,-3.0e38f}};
    float lI[2][4] = {};

    const int nkt = 2 * qt + 2;
    for (int kt = 0; kt < nkt; ++kt) {
        const float* ktb = kb + (size_t)kt * 64 * 64;
        const float* vtb = vb + (size_t)kt * 64 * 64;
        __syncthreads();   // prev PV reads of KPs/Vs complete
        #pragma unroll
        for (int j = 0; j < 4; ++j) {
            int job = tid + j * 256;       // 0..1023
            int row = job >> 4, d4 = job & 15, dd = d4 * 4;
            float4 kv4 = *(const float4*)(ktb + row * 64 + d4 * 4);
            KPs[swz64(dd + 0, row)] = kv4.x;
            KPs[swz64(dd + 1, row)] = kv4.y;
            KPs[swz64(dd + 2, row)] = kv4.z;
            KPs[swz64(dd + 3, row)] = kv4.w;
            *(float4*)&Vs[row * 64 + d4 * 4] = *(const float4*)(vtb + row * 64 + d4 * 4);
        }
        __syncthreads();

        // S = Q K^T (128x64x64)
        float S[2][4][4] = {};
        #pragma unroll 8
        for (int d = 0; d < 64; ++d) {
            float4 a0 = *(const float4*)&Qs[swz128(d, m0)];
            float4 a1 = *(const float4*)&Qs[swz128(d, m0 + 64)];
            float4 bq = *(const float4*)&KPs[swz64(d, n0)];
            S[0][0][0] += a0.x * bq.x; S[0][0][1] += a0.x * bq.y; S[0][0][2] += a0.x * bq.z; S[0][0][3] += a0.x * bq.w;
            S[0][1][0] += a0.y * bq.x; S[0][1][1] += a0.y * bq.y; S[0][1][2] += a0.y * bq.z; S[0][1][3] += a0.y * bq.w;
            S[0][2][0] += a0.z * bq.x; S[0][2][1] += a0.z * bq.y; S[0][2][2] += a0.z * bq.z; S[0][2][3] += a0.z * bq.w;
            S[0][3][0] += a0.w * bq.x; S[0][3][1] += a0.w * bq.y; S[0][3][2] += a0.w * bq.z; S[0][3][3] += a0.w * bq.w;
            S[1][0][0] += a1.x * bq.x; S[1][0][1] += a1.x * bq.y; S[1][0][2] += a1.x * bq.z; S[1][0][3] += a1.x * bq.w;
            S[1][1][0] += a1.y * bq.x; S[1][1][1] += a1.y * bq.y; S[1][1][2] += a1.y * bq.z; S[1][1][3] += a1.y * bq.w;
            S[1][2][0] += a1.z * bq.x; S[1][2][1] += a1.z * bq.y; S[1][2][2] += a1.z * bq.z; S[1][2][3] += a1.z * bq.w;
            S[1][3][0] += a1.w * bq.x; S[1][3][1] += a1.w * bq.y; S[1][3][2] += a1.w * bq.z; S[1][3][3] += a1.w * bq.w;
        }

        if (kt >= 2 * qt) {   // diagonal tiles: causal mask on global indices
            const int colg0 = kt * 64 + n0;
            #pragma unroll
            for (int ri = 0; ri < 2; ++ri) {
                const int rowg0 = qt * 128 + ri * 64 + m0;
                #pragma unroll
                for (int i = 0; i < 4; ++i)
                    #pragma unroll
                    for (int j = 0; j < 4; ++j)
                        if (colg0 + j > rowg0 + i) S[ri][i][j] = -1e30f;
            }
        }

        // online softmax (row stats across the 16 lanes of a row group)
        #pragma unroll
        for (int ri = 0; ri < 2; ++ri)
            #pragma unroll
            for (int i = 0; i < 4; ++i) {
                float mt = fmaxf(fmaxf(S[ri][i][0], S[ri][i][1]), fmaxf(S[ri][i][2], S[ri][i][3]));
                #pragma unroll
                for (int off = 8; off; off >>= 1)
                    mt = fmaxf(mt, __shfl_xor_sync(0xffffffffu, mt, off, 16));
                float mn = fmaxf(mI[ri][i], mt);
                float alpha = __expf(mI[ri][i] - mn);
                mI[ri][i] = mn;
                float sum = 0.f;
                #pragma unroll
                for (int j = 0; j < 4; ++j) { S[ri][i][j] = __expf(S[ri][i][j] - mn); sum += S[ri][i][j]; }
                #pragma unroll
                for (int off = 8; off; off >>= 1)
                    sum += __shfl_xor_sync(0xffffffffu, sum, off, 16);
                lI[ri][i] = lI[ri][i] * alpha + sum;
                #pragma unroll
                for (int j = 0; j < 4; ++j) O[ri][i][j] *= alpha;
            }

        __syncthreads();   // everyone done reading K from KPs
        // write P transposed: KPs[k][m] swizzled (overwrites K region)
        #pragma unroll
        for (int ri = 0; ri < 2; ++ri)
            #pragma unroll
            for (int i = 0; i < 4; ++i)
                #pragma unroll
                for (int j = 0; j < 4; ++j)
                    KPs[swz128(n0 + j, ri * 64 + m0 + i)] = S[ri][i][j];
        __syncthreads();

        // O += P V  (128x64x64)
        #pragma unroll 8
        for (int d = 0; d < 64; ++d) {
            float4 a0 = *(const float4*)&KPs[swz128(d, m0)];
            float4 a1 = *(const float4*)&KPs[swz128(d, m0 + 64)];
            float4 bv = *(const float4*)&Vs[d * 64 + n0];
            O[0][0][0] += a0.x * bv.x; O[0][0][1] += a0.x * bv.y; O[0][0][2] += a0.x * bv.z; O[0][0][3] += a0.x * bv.w;
            O[0][1][0] += a0.y * bv.x; O[0][1][1] += a0.y * bv.y; O[0][1][2] += a0.y * bv.z; O[0][1][3] += a0.y * bv.w;
            O[0][2][0] += a0.z * bv.x; O[0][2][1] += a0.z * bv.y; O[0][2][2] += a0.z * bv.z; O[0][2][3] += a0.z * bv.w;
            O[0][3][0] += a0.w * bv.x; O[0][3][1] += a0.w * bv.y; O[0][3][2] += a0.w * bv.z; O[0][3][3] += a0.w * bv.w;
            O[1][0][0] += a1.x * bv.x; O[1][0][1] += a1.x * bv.y; O[1][0][2] += a1.x * bv.z; O[1][0][3] += a1.x * bv.w;
            O[1][1][0] += a1.y * bv.x; O[1][1][1] += a1.y * bv.y; O[1][1][2] += a1.y * bv.z; O[1][1][3] += a1.y * bv.w;
            O[1][2][0] += a1.z * bv.x; O[1][2][1] += a1.z * bv.y; O[1][2][2] += a1.z * bv.z; O[1][2][3] += a1.z * bv.w;
            O[1][3][0] += a1.w * bv.x; O[1][3][1] += a1.w * bv.y; O[1][3][2] += a1.w * bv.z; O[1][3][3] += a1.w * bv.w;
        }
    }

    // epilogue: normalize, add value-residual, write [B*T, 512]
    #pragma unroll
    for (int ri = 0; ri < 2; ++ri)
        #pragma unroll
        for (int i = 0; i < 4; ++i) {
            float invl = 1.0f / lI[ri][i];
            size_t grow = ((size_t)b * Tt + qt * 128 + ri * 64 + m0 + i) * 512 + h * 64 + n0;
            float4 vr = *(const float4*)(vres + grow);
            float4 o;
            o.x = O[ri][i][0] * invl + vr.x;
            o.y = O[ri][i][1] * invl + vr.y;
            o.z = O[ri][i][2] * invl + vr.z;
            o.w = O[ri][i][3] * invl + vr.w;
            *(float4*)(out + grow) = o;
        }
}

// ---------------------------------------------------------------------------
extern "C" void kernel_launch(void* const* d_in, const int* in_sizes, int n_in,
                              void* d_out, int out_size)
{
    const float* x    = (const float*)d_in[0];
    const float* WDQ  = (const float*)d_in[1];
    const float* WUQ  = (const float*)d_in[2];
    const float* WQR  = (const float*)d_in[3];
    const float* WDKV = (const float*)d_in[4];
    const float* WUK  = (const float*)d_in[5];
    const float* WUV  = (const float*)d_in[6];
    const float* WKR  = (const float*)d_in[7];
    const float* WVR  = (const float*)d_in[8];
    const float* WO   = (const float*)d_in[9];
    const float* qlnw = (const float*)d_in[10];
    const float* kvlnw= (const float*)d_in[11];
    const float* qhw  = (const float*)d_in[12];
    const float* khw  = (const float*)d_in[13];
    float* out = (float*)d_out;

    float *cq, *qn, *qr, *ckv, *kn, *kr, *vraw, *vres, *q, *k, *v, *ao;
    cudaGetSymbolAddress((void**)&cq,   g_cq);
    cudaGetSymbolAddress((void**)&qn,   g_qn);
    cudaGetSymbolAddress((void**)&qr,   g_qr);
    cudaGetSymbolAddress((void**)&ckv,  g_ckv);
    cudaGetSymbolAddress((void**)&kn,   g_kn);
    cudaGetSymbolAddress((void**)&kr,   g_kr);
    cudaGetSymbolAddress((void**)&vraw, g_vraw);
    cudaGetSymbolAddress((void**)&vres, g_vres);
    cudaGetSymbolAddress((void**)&q,    g_q);
    cudaGetSymbolAddress((void**)&k,    g_k);
    cudaGetSymbolAddress((void**)&v,    g_v);
    cudaGetSymbolAddress((void**)&ao,   g_ao);

    const int FLASH_SMEM = (2 * 64 * 128 + 64 * 64) * sizeof(float);  // 80KB
    cudaFuncSetAttribute(flash128, cudaFuncAttributeMaxDynamicSharedMemorySize, FLASH_SMEM);

    // Q path
    sgemm128<<<dim3(2, 64), 256>>>(x, WDQ, cq, BT, 256, 512);
    rms_inplace<<<BT, 128>>>(cq, qlnw, 256);
    sgemm128<<<dim3(2, 64), 256>>>(cq, WUQ, qn, BT, 256, 256);
    sgemm128<<<dim3(2, 64), 256>>>(cq, WQR, qr, BT, 256, 256);
    // KV path
    sgemm128<<<dim3(1, 64), 256>>>(x, WDKV, ckv, BT, 128, 512);
    rms_inplace<<<BT, 128>>>(ckv, kvlnw, 128);
    sgemm64<<<dim3(1, 128), 256>>>(ckv, WUK, kn, BT, 64, 128);
    sgemm128<<<dim3(1, 64), 256>>>(ckv, WUV, vraw, BT, 128, 128);
    sgemm64<<<dim3(1, 128), 256>>>(x, WKR, kr, BT, 64, 512);
    // value residual
    sgemm128<<<dim3(4, 64), 256>>>(x, WVR, vres, BT, 512, 512);
    // rope + head-norm + layout
    assemble<<<dim3(Tt, Bb), 256>>>(qn, qr, kn, kr, vraw, qhw, khw, q, k, v);
    // causal flash attention (+ residual add)
    flash128<<<dim3(Tt/128, Hh, Bb), 256, FLASH_SMEM>>>(q, k, v, vres, ao);
    // output projection
    sgemm128<<<dim3(4, 64), 256>>>(ao, WO, out, BT, 512, 512);
}

// round 6
// speedup vs baseline: 1.5997x; 1.5997x over previous
#include <cuda_runtime.h>
#include <cuda_bf16.h>
#include <math.h>
#include <cstdint>
#include <cstring>

// ---------------------------------------------------------------------------
// MLA attention pipeline. B=4, T=2048, D=512, H=8, KVH=2, HD=64
// Round 6 (resubmit of R5; prior round was an infra failure):
// flash attention on HMMA (mma.sync m16n8k16 bf16, 3-term split, fp32 accum).
// Projections stay on the proven fp32 sgemm kernels.
// NOTE: harness targets plain sm_100 -> tcgen05 unavailable; mma.sync is the
// tensor-core path.
// ---------------------------------------------------------------------------

#define Bb   4
#define Tt   2048
#define Hh   8
#define KVHh 2
#define BT   (Bb*Tt)      // 8192
#define EPSF 1e-6f

// ------------------------- scratch (device globals) ------------------------
__device__ float g_cq  [BT*256];
__device__ float g_qn  [BT*256];
__device__ float g_qr  [BT*256];
__device__ float g_ckv [BT*128];
__device__ float g_kn  [BT*64];
__device__ float g_kr  [BT*64];
__device__ float g_vraw[BT*128];
__device__ float g_vres[BT*512];
__device__ float g_q   [BT*512];
__device__ float g_k   [Bb*KVHh*Tt*64];
__device__ float g_v   [Bb*KVHh*Tt*64];
__device__ float g_ao  [BT*512];

// ---------------------------------------------------------------------------
// SGEMM 64x64 (N%64). M%64==0, N%64==0, K%16==0.
// ---------------------------------------------------------------------------
__global__ __launch_bounds__(256) void sgemm64(
    const float* __restrict__ A, const float* __restrict__ B,
    float* __restrict__ C, int M, int N, int K)
{
    __shared__ float As[16][64];
    __shared__ float Bs[16][64];

    const int bm = blockIdx.y * 64;
    const int bn = blockIdx.x * 64;
    const int tid = threadIdx.x;
    const int ty = tid >> 4, tx = tid & 15;
    const int am = tid >> 2, ak4 = tid & 3;
    const int bk = tid >> 4, bn4 = tid & 15;

    float acc[4][4] = {};

    for (int k0 = 0; k0 < K; k0 += 16) {
        float4 av = *(const float4*)(A + (size_t)(bm + am) * K + k0 + ak4 * 4);
        float4 bv = *(const float4*)(B + (size_t)(k0 + bk) * N + bn + bn4 * 4);
        __syncthreads();
        As[ak4 * 4 + 0][am] = av.x;
        As[ak4 * 4 + 1][am] = av.y;
        As[ak4 * 4 + 2][am] = av.z;
        As[ak4 * 4 + 3][am] = av.w;
        *(float4*)&Bs[bk][bn4 * 4] = bv;
        __syncthreads();
        #pragma unroll
        for (int kk = 0; kk < 16; ++kk) {
            float4 a = *(const float4*)&As[kk][ty * 4];
            float4 b = *(const float4*)&Bs[kk][tx * 4];
            acc[0][0] += a.x * b.x; acc[0][1] += a.x * b.y; acc[0][2] += a.x * b.z; acc[0][3] += a.x * b.w;
            acc[1][0] += a.y * b.x; acc[1][1] += a.y * b.y; acc[1][2] += a.y * b.z; acc[1][3] += a.y * b.w;
            acc[2][0] += a.z * b.x; acc[2][1] += a.z * b.y; acc[2][2] += a.z * b.z; acc[2][3] += a.z * b.w;
            acc[3][0] += a.w * b.x; acc[3][1] += a.w * b.y; acc[3][2] += a.w * b.z; acc[3][3] += a.w * b.w;
        }
    }

    #pragma unroll
    for (int i = 0; i < 4; ++i) {
        float4 o = make_float4(acc[i][0], acc[i][1], acc[i][2], acc[i][3]);
        *(float4*)(C + (size_t)(bm + ty * 4 + i) * N + bn + tx * 4) = o;
    }
}

// ---------------------------------------------------------------------------
// SGEMM 128x128 tile, BK=8, 256 threads.
// ---------------------------------------------------------------------------
__global__ __launch_bounds__(256) void sgemm128(
    const float* __restrict__ A, const float* __restrict__ B,
    float* __restrict__ C, int M, int N, int K)
{
    __shared__ float As[8][128];
    __shared__ float Bs[8][128];

    const int bm = blockIdx.y * 128;
    const int bn = blockIdx.x * 128;
    const int tid = threadIdx.x;
    const int ty = tid >> 4, tx = tid & 15;
    const int arow = tid >> 1, ak = (tid & 1) * 4;
    const int bk = tid >> 5, bcol = (tid & 31) * 4;

    float acc[2][2][4][4] = {};

    for (int k0 = 0; k0 < K; k0 += 8) {
        float4 av = *(const float4*)(A + (size_t)(bm + arow) * K + k0 + ak);
        float4 bv = *(const float4*)(B + (size_t)(k0 + bk) * N + bn + bcol);
        __syncthreads();
        As[ak + 0][arow] = av.x;
        As[ak + 1][arow] = av.y;
        As[ak + 2][arow] = av.z;
        As[ak + 3][arow] = av.w;
        *(float4*)&Bs[bk][bcol] = bv;
        __syncthreads();
        #pragma unroll
        for (int kk = 0; kk < 8; ++kk) {
            float4 a0 = *(const float4*)&As[kk][ty * 4];
            float4 a1 = *(const float4*)&As[kk][64 + ty * 4];
            float4 b0 = *(const float4*)&Bs[kk][tx * 4];
            float4 b1 = *(const float4*)&Bs[kk][64 + tx * 4];
            #pragma unroll
            for (int ri = 0; ri < 2; ++ri) {
                float4 a = ri ? a1 : a0;
                #pragma unroll
                for (int ci = 0; ci < 2; ++ci) {
                    float4 b = ci ? b1 : b0;
                    acc[ri][ci][0][0] += a.x * b.x; acc[ri][ci][0][1] += a.x * b.y;
                    acc[ri][ci][0][2] += a.x * b.z; acc[ri][ci][0][3] += a.x * b.w;
                    acc[ri][ci][1][0] += a.y * b.x; acc[ri][ci][1][1] += a.y * b.y;
                    acc[ri][ci][1][2] += a.y * b.z; acc[ri][ci][1][3] += a.y * b.w;
                    acc[ri][ci][2][0] += a.z * b.x; acc[ri][ci][2][1] += a.z * b.y;
                    acc[ri][ci][2][2] += a.z * b.z; acc[ri][ci][2][3] += a.z * b.w;
                    acc[ri][ci][3][0] += a.w * b.x; acc[ri][ci][3][1] += a.w * b.y;
                    acc[ri][ci][3][2] += a.w * b.z; acc[ri][ci][3][3] += a.w * b.w;
                }
            }
        }
    }

    #pragma unroll
    for (int ri = 0; ri < 2; ++ri)
        #pragma unroll
        for (int i = 0; i < 4; ++i) {
            size_t row = (size_t)(bm + ri * 64 + ty * 4 + i);
            #pragma unroll
            for (int ci = 0; ci < 2; ++ci) {
                float4 o = make_float4(acc[ri][ci][i][0], acc[ri][ci][i][1],
                                       acc[ri][ci][i][2], acc[ri][ci][i][3]);
                *(float4*)(C + row * N + bn + ci * 64 + tx * 4) = o;
            }
        }
}

// ---------------------------------------------------------------------------
// In-place RMSNorm over rows of length `dim`.
// ---------------------------------------------------------------------------
__global__ __launch_bounds__(128) void rms_inplace(
    float* __restrict__ x, const float* __restrict__ w, int dim)
{
    const int row = blockIdx.x;
    float* xr = x + (size_t)row * dim;
    float ss = 0.f;
    for (int i = threadIdx.x; i < dim; i += 128) { float v = xr[i]; ss += v * v; }
    #pragma unroll
    for (int off = 16; off; off >>= 1) ss += __shfl_xor_sync(0xffffffffu, ss, off);
    __shared__ float sred[4];
    if ((threadIdx.x & 31) == 0) sred[threadIdx.x >> 5] = ss;
    __syncthreads();
    float tot = sred[0] + sred[1] + sred[2] + sred[3];
    float rr = rsqrtf(tot / (float)dim + EPSF);
    for (int i = threadIdx.x; i < dim; i += 128) xr[i] = xr[i] * rr * w[i];
}

// ---------------------------------------------------------------------------
// Assemble: RoPE + concat + per-head RMSNorm + layout to [B,h,T,64].
// ---------------------------------------------------------------------------
__global__ __launch_bounds__(256) void assemble(
    const float* __restrict__ qn, const float* __restrict__ qr,
    const float* __restrict__ kn, const float* __restrict__ kr,
    const float* __restrict__ vraw,
    const float* __restrict__ qhw, const float* __restrict__ khw,
    float* __restrict__ q, float* __restrict__ k, float* __restrict__ v)
{
    const int t = blockIdx.x, b = blockIdx.y;
    const int row = b * Tt + t;
    const int w = threadIdx.x >> 5, lane = threadIdx.x & 31;

    const int fi = lane & 15;
    float invf = (float)exp(-((double)fi / 16.0) * log(500000.0));
    float ph = (float)t * invf;
    float sv, cv;
    sincosf(ph, &sv, &cv);

    {
        const int h = w;
        const float* qnr = qn + (size_t)row * 256 + h * 32;
        const float* qrr = qr + (size_t)row * 256 + h * 32;
        float v0 = qnr[lane];
        float x1 = qrr[lane];
        float xr_ = (lane < 16) ? -qrr[lane + 16] : qrr[lane - 16];
        float v1 = x1 * cv + xr_ * sv;
        float ss = v0 * v0 + v1 * v1;
        #pragma unroll
        for (int off = 16; off; off >>= 1) ss += __shfl_xor_sync(0xffffffffu, ss, off);
        float rr = rsqrtf(ss / 64.0f + EPSF);
        float* qo = q + ((size_t)(b * Hh + h) * Tt + t) * 64;
        qo[lane]      = v0 * rr * qhw[lane];
        qo[lane + 32] = v1 * rr * qhw[lane + 32];
    }

    if (w < KVHh) {
        const int kvh = w;
        const float* knr = kn + (size_t)row * 64 + kvh * 32;
        const float* krr = kr + (size_t)row * 64 + kvh * 32;
        float v0 = knr[lane];
        float x1 = krr[lane];
        float xr_ = (lane < 16) ? -krr[lane + 16] : krr[lane - 16];
        float v1 = x1 * cv + xr_ * sv;
        float ss = v0 * v0 + v1 * v1;
        #pragma unroll
        for (int off = 16; off; off >>= 1) ss += __shfl_xor_sync(0xffffffffu, ss, off);
        float rr = rsqrtf(ss / 64.0f + EPSF);
        float* ko = k + ((size_t)(b * KVHh + kvh) * Tt + t) * 64;
        ko[lane]      = v0 * rr * khw[lane];
        ko[lane + 32] = v1 * rr * khw[lane + 32];
    }

    for (int i = threadIdx.x; i < 128; i += 256) {
        int kvh = i >> 6, d = i & 63;
        v[((size_t)(b * KVHh + kvh) * Tt + t) * 64 + d] = vraw[(size_t)row * 128 + i];
    }
}

// ---------------------------------------------------------------------------
// mma.sync m16n8k16, row.col, bf16 x bf16 -> fp32
// ---------------------------------------------------------------------------
__device__ __forceinline__ void mma16816(
    float* d, const uint32_t* a, const uint32_t* b)
{
    asm volatile(
        "mma.sync.aligned.m16n8k16.row.col.f32.bf16.bf16.f32 "
        "{%0,%1,%2,%3}, {%4,%5,%6,%7}, {%8,%9}, {%0,%1,%2,%3};"
        : "+f"(d[0]), "+f"(d[1]), "+f"(d[2]), "+f"(d[3])
        : "r"(a[0]), "r"(a[1]), "r"(a[2]), "r"(a[3]), "r"(b[0]), "r"(b[1]));
}

__device__ __forceinline__ uint32_t pack_bf16(float lo, float hi) {
    __nv_bfloat162 p = __floats2bfloat162_rn(lo, hi);
    uint32_t u; memcpy(&u, &p, 4);
    return u;
}

// ---------------------------------------------------------------------------
// Flash attention on HMMA, bf16 3-term split, fp32 accum.
// Tile: BM=64 (4 warps x 16 rows), BN=64 kv. 128 threads.
// Smem K/V tiles: bf16 hi/lo, row stride 72 bf16 (36 words) -> conflict-free
// fragment loads. P stays in registers (C-frag -> A-frag identity).
// Grid (T/64, H, B), heavy-first qt ordering.
// ---------------------------------------------------------------------------
__global__ __launch_bounds__(128) void flash_mma(
    const float* __restrict__ Q, const float* __restrict__ Kk,
    const float* __restrict__ V, const float* __restrict__ vres,
    float* __restrict__ out)
{
    __shared__ uint32_t sKhi[64 * 36];
    __shared__ uint32_t sKlo[64 * 36];
    __shared__ uint32_t sVhi[64 * 36];
    __shared__ uint32_t sVlo[64 * 36];

    const int qt = (Tt / 64 - 1) - blockIdx.x;   // heavy blocks first
    const int h = blockIdx.y, b = blockIdx.z;
    const int kvh = h >> 2;
    const float* qbase = Q  + (((size_t)b * Hh   + h)   * Tt + qt * 64) * 64;
    const float* kb    = Kk + (((size_t)b * KVHh + kvh) * Tt) * 64;
    const float* vb    = V  + (((size_t)b * KVHh + kvh) * Tt) * 64;

    const int tid  = threadIdx.x;
    const int w    = tid >> 5;
    const int lane = tid & 31;
    const int g    = lane >> 2;      // groupID (row within 8)
    const int t    = lane & 3;       // threadInGroup (col pair)

    // ---- Q fragments (built once): a-frag per k-step, hi+lo split ----
    uint32_t qhi[4][4], qlo[4][4];
    {
        const float* r0 = qbase + (size_t)(w * 16 + g) * 64;
        const float* r1 = r0 + 8 * 64;
        #pragma unroll
        for (int ks = 0; ks < 4; ++ks) {
            float2 x0 = *(const float2*)(r0 + ks * 16 + 2 * t);
            float2 x1 = *(const float2*)(r1 + ks * 16 + 2 * t);
            float2 x2 = *(const float2*)(r0 + ks * 16 + 8 + 2 * t);
            float2 x3 = *(const float2*)(r1 + ks * 16 + 8 + 2 * t);
            float f[8] = {x0.x, x0.y, x1.x, x1.y, x2.x, x2.y, x3.x, x3.y};
            #pragma unroll
            for (int i = 0; i < 8; ++i) f[i] *= 0.125f;
            float hi[8], lo[8];
            #pragma unroll
            for (int i = 0; i < 8; ++i) {
                hi[i] = __bfloat162float(__float2bfloat16(f[i]));
                lo[i] = f[i] - hi[i];
            }
            #pragma unroll
            for (int r = 0; r < 4; ++r) {
                qhi[ks][r] = pack_bf16(hi[2*r], hi[2*r+1]);
                qlo[ks][r] = pack_bf16(lo[2*r], lo[2*r+1]);
            }
        }
    }

    float O[8][4];
    #pragma unroll
    for (int i = 0; i < 8; ++i)
        #pragma unroll
        for (int j = 0; j < 4; ++j) O[i][j] = 0.f;
    float mI[2] = {-3.0e38f, -3.0e38f};
    float lI[2] = {0.f, 0.f};

    for (int kt = 0; kt <= qt; ++kt) {
        const float* ktb = kb + (size_t)kt * 64 * 64;
        const float* vtb = vb + (size_t)kt * 64 * 64;
        __syncthreads();
        // fill K/V tiles: fp32 -> bf16 hi/lo, row stride 36 words
        #pragma unroll
        for (int it = 0; it < 8; ++it) {
            int idx = tid + it * 128;           // 0..1023
            int row = idx >> 4, c4 = idx & 15;
            int so = row * 36 + c4 * 2;
            float4 kv4 = *(const float4*)(ktb + row * 64 + c4 * 4);
            float h0 = __bfloat162float(__float2bfloat16(kv4.x));
            float h1 = __bfloat162float(__float2bfloat16(kv4.y));
            float h2 = __bfloat162float(__float2bfloat16(kv4.z));
            float h3 = __bfloat162float(__float2bfloat16(kv4.w));
            sKhi[so]     = pack_bf16(h0, h1);
            sKhi[so + 1] = pack_bf16(h2, h3);
            sKlo[so]     = pack_bf16(kv4.x - h0, kv4.y - h1);
            sKlo[so + 1] = pack_bf16(kv4.z - h2, kv4.w - h3);
            float4 vv4 = *(const float4*)(vtb + row * 64 + c4 * 4);
            h0 = __bfloat162float(__float2bfloat16(vv4.x));
            h1 = __bfloat162float(__float2bfloat16(vv4.y));
            h2 = __bfloat162float(__float2bfloat16(vv4.z));
            h3 = __bfloat162float(__float2bfloat16(vv4.w));
            sVhi[so]     = pack_bf16(h0, h1);
            sVhi[so + 1] = pack_bf16(h2, h3);
            sVlo[so]     = pack_bf16(vv4.x - h0, vv4.y - h1);
            sVlo[so + 1] = pack_bf16(vv4.z - h2, vv4.w - h3);
        }
        __syncthreads();

        // ---- S = Q K^T : 16x64, 8 n-tiles ----
        float S[8][4];
        #pragma unroll
        for (int nt = 0; nt < 8; ++nt) {
            float* sa = S[nt];
            sa[0] = sa[1] = sa[2] = sa[3] = 0.f;
            const int nrow = nt * 8 + g;
            #pragma unroll
            for (int ks = 0; ks < 4; ++ks) {
                uint32_t bhi[2], blo[2];
                int base = nrow * 36 + ks * 8 + t;
                bhi[0] = sKhi[base];     bhi[1] = sKhi[base + 4];
                blo[0] = sKlo[base];     blo[1] = sKlo[base + 4];
                mma16816(sa, qhi[ks], bhi);
                mma16816(sa, qlo[ks], bhi);
                mma16816(sa, qhi[ks], blo);
            }
        }

        // causal mask on the diagonal tile
        if (kt == qt) {
            const int rg0 = w * 16 + g;
            #pragma unroll
            for (int nt = 0; nt < 8; ++nt) {
                int c0 = nt * 8 + 2 * t;
                if (c0 > rg0)     S[nt][0] = -1e30f;
                if (c0 + 1 > rg0) S[nt][1] = -1e30f;
                if (c0 > rg0 + 8)     S[nt][2] = -1e30f;
                if (c0 + 1 > rg0 + 8) S[nt][3] = -1e30f;
            }
        }

        // ---- online softmax: rows g (S[..][0,1]) and g+8 (S[..][2,3]) ----
        float mt0 = -3.0e38f, mt1 = -3.0e38f;
        #pragma unroll
        for (int nt = 0; nt < 8; ++nt) {
            mt0 = fmaxf(mt0, fmaxf(S[nt][0], S[nt][1]));
            mt1 = fmaxf(mt1, fmaxf(S[nt][2], S[nt][3]));
        }
        mt0 = fmaxf(mt0, __shfl_xor_sync(0xffffffffu, mt0, 1));
        mt0 = fmaxf(mt0, __shfl_xor_sync(0xffffffffu, mt0, 2));
        mt1 = fmaxf(mt1, __shfl_xor_sync(0xffffffffu, mt1, 1));
        mt1 = fmaxf(mt1, __shfl_xor_sync(0xffffffffu, mt1, 2));
        float mn0 = fmaxf(mI[0], mt0), mn1 = fmaxf(mI[1], mt1);
        float al0 = __expf(mI[0] - mn0), al1 = __expf(mI[1] - mn1);
        mI[0] = mn0; mI[1] = mn1;

        float sum0 = 0.f, sum1 = 0.f;
        #pragma unroll
        for (int nt = 0; nt < 8; ++nt) {
            S[nt][0] = __expf(S[nt][0] - mn0); sum0 += S[nt][0];
            S[nt][1] = __expf(S[nt][1] - mn0); sum0 += S[nt][1];
            S[nt][2] = __expf(S[nt][2] - mn1); sum1 += S[nt][2];
            S[nt][3] = __expf(S[nt][3] - mn1); sum1 += S[nt][3];
        }
        sum0 += __shfl_xor_sync(0xffffffffu, sum0, 1);
        sum0 += __shfl_xor_sync(0xffffffffu, sum0, 2);
        sum1 += __shfl_xor_sync(0xffffffffu, sum1, 1);
        sum1 += __shfl_xor_sync(0xffffffffu, sum1, 2);
        lI[0] = lI[0] * al0 + sum0;
        lI[1] = lI[1] * al1 + sum1;
        #pragma unroll
        for (int dt = 0; dt < 8; ++dt) {
            O[dt][0] *= al0; O[dt][1] *= al0;
            O[dt][2] *= al1; O[dt][3] *= al1;
        }

        // ---- P fragments from S (C-frag -> A-frag identity), hi/lo split ----
        uint32_t phi[8][2], plo[8][2];
        #pragma unroll
        for (int nt = 0; nt < 8; ++nt) {
            float h0 = __bfloat162float(__float2bfloat16(S[nt][0]));
            float h1 = __bfloat162float(__float2bfloat16(S[nt][1]));
            float h2 = __bfloat162float(__float2bfloat16(S[nt][2]));
            float h3 = __bfloat162float(__float2bfloat16(S[nt][3]));
            phi[nt][0] = pack_bf16(h0, h1);
            phi[nt][1] = pack_bf16(h2, h3);
            plo[nt][0] = pack_bf16(S[nt][0] - h0, S[nt][1] - h1);
            plo[nt][1] = pack_bf16(S[nt][2] - h2, S[nt][3] - h3);
        }

        // ---- O += P V : 16x64, k=kv ----
        #pragma unroll
        for (int ks = 0; ks < 4; ++ks) {
            uint32_t aP[4] = {phi[2*ks][0], phi[2*ks][1], phi[2*ks+1][0], phi[2*ks+1][1]};
            uint32_t aL[4] = {plo[2*ks][0], plo[2*ks][1], plo[2*ks+1][0], plo[2*ks+1][1]};
            const int r0 = ks * 16 + 2 * t;
            #pragma unroll
            for (int dt = 0; dt < 8; ++dt) {
                const int n = dt * 8 + g;
                const __nv_bfloat16* vh = (const __nv_bfloat16*)sVhi;
                const __nv_bfloat16* vl = (const __nv_bfloat16*)sVlo;
                uint32_t bhi[2], blo[2];
                bhi[0] = pack_bf16(__bfloat162float(vh[(r0    ) * 72 + n]),
                                   __bfloat162float(vh[(r0 + 1) * 72 + n]));
                bhi[1] = pack_bf16(__bfloat162float(vh[(r0 + 8) * 72 + n]),
                                   __bfloat162float(vh[(r0 + 9) * 72 + n]));
                blo[0] = pack_bf16(__bfloat162float(vl[(r0    ) * 72 + n]),
                                   __bfloat162float(vl[(r0 + 1) * 72 + n]));
                blo[1] = pack_bf16(__bfloat162float(vl[(r0 + 8) * 72 + n]),
                                   __bfloat162float(vl[(r0 + 9) * 72 + n]));
                mma16816(O[dt], aP, bhi);
                mma16816(O[dt], aL, bhi);
                mma16816(O[dt], aP, blo);
            }
        }
    }

    // ---- epilogue: normalize, add v_res, write [B*T, 512] ----
    const float inv0 = 1.0f / lI[0];
    const float inv1 = 1.0f / lI[1];
    const size_t row0 = (size_t)b * Tt + qt * 64 + w * 16 + g;
    const size_t row1 = row0 + 8;
    #pragma unroll
    for (int dt = 0; dt < 8; ++dt) {
        const int col = h * 64 + dt * 8 + 2 * t;
        float2 vr0 = *(const float2*)(vres + row0 * 512 + col);
        float2 vr1 = *(const float2*)(vres + row1 * 512 + col);
        float2 o0 = make_float2(O[dt][0] * inv0 + vr0.x, O[dt][1] * inv0 + vr0.y);
        float2 o1 = make_float2(O[dt][2] * inv1 + vr1.x, O[dt][3] * inv1 + vr1.y);
        *(float2*)(out + row0 * 512 + col) = o0;
        *(float2*)(out + row1 * 512 + col) = o1;
    }
}

// ---------------------------------------------------------------------------
extern "C" void kernel_launch(void* const* d_in, const int* in_sizes, int n_in,
                              void* d_out, int out_size)
{
    const float* x    = (const float*)d_in[0];
    const float* WDQ  = (const float*)d_in[1];
    const float* WUQ  = (const float*)d_in[2];
    const float* WQR  = (const float*)d_in[3];
    const float* WDKV = (const float*)d_in[4];
    const float* WUK  = (const float*)d_in[5];
    const float* WUV  = (const float*)d_in[6];
    const float* WKR  = (const float*)d_in[7];
    const float* WVR  = (const float*)d_in[8];
    const float* WO   = (const float*)d_in[9];
    const float* qlnw = (const float*)d_in[10];
    const float* kvlnw= (const float*)d_in[11];
    const float* qhw  = (const float*)d_in[12];
    const float* khw  = (const float*)d_in[13];
    float* out = (float*)d_out;

    float *cq, *qn, *qr, *ckv, *kn, *kr, *vraw, *vres, *q, *k, *v, *ao;
    cudaGetSymbolAddress((void**)&cq,   g_cq);
    cudaGetSymbolAddress((void**)&qn,   g_qn);
    cudaGetSymbolAddress((void**)&qr,   g_qr);
    cudaGetSymbolAddress((void**)&ckv,  g_ckv);
    cudaGetSymbolAddress((void**)&kn,   g_kn);
    cudaGetSymbolAddress((void**)&kr,   g_kr);
    cudaGetSymbolAddress((void**)&vraw, g_vraw);
    cudaGetSymbolAddress((void**)&vres, g_vres);
    cudaGetSymbolAddress((void**)&q,    g_q);
    cudaGetSymbolAddress((void**)&k,    g_k);
    cudaGetSymbolAddress((void**)&v,    g_v);
    cudaGetSymbolAddress((void**)&ao,   g_ao);

    // Q path
    sgemm128<<<dim3(2, 64), 256>>>(x, WDQ, cq, BT, 256, 512);
    rms_inplace<<<BT, 128>>>(cq, qlnw, 256);
    sgemm128<<<dim3(2, 64), 256>>>(cq, WUQ, qn, BT, 256, 256);
    sgemm128<<<dim3(2, 64), 256>>>(cq, WQR, qr, BT, 256, 256);
    // KV path
    sgemm128<<<dim3(1, 64), 256>>>(x, WDKV, ckv, BT, 128, 512);
    rms_inplace<<<BT, 128>>>(ckv, kvlnw, 128);
    sgemm64<<<dim3(1, 128), 256>>>(ckv, WUK, kn, BT, 64, 128);
    sgemm128<<<dim3(1, 64), 256>>>(ckv, WUV, vraw, BT, 128, 128);
    sgemm64<<<dim3(1, 128), 256>>>(x, WKR, kr, BT, 64, 512);
    // value residual
    sgemm128<<<dim3(4, 64), 256>>>(x, WVR, vres, BT, 512, 512);
    // rope + head-norm + layout
    assemble<<<dim3(Tt, Bb), 256>>>(qn, qr, kn, kr, vraw, qhw, khw, q, k, v);
    // causal flash attention on HMMA (+ residual add)
    flash_mma<<<dim3(Tt/64, Hh, Bb), 128>>>(q, k, v, vres, ao);
    // output projection
    sgemm128<<<dim3(4, 64), 256>>>(ao, WO, out, BT, 512, 512);
}

// round 7
// speedup vs baseline: 2.2039x; 1.3777x over previous
#include <cuda_runtime.h>
#include <cuda_bf16.h>
#include <math.h>
#include <cstdint>
#include <cstring>

// ---------------------------------------------------------------------------
// MLA attention pipeline. B=4, T=2048, D=512, H=8, KVH=2, HD=64
// Round 7: everything heavy on HMMA (mma.sync m16n8k16 bf16, 3-term split,
// fp32 accum). Activations/weights pre-split to bf16 hi/lo; assemble emits
// K/V directly as bf16 hi/lo so flash's inner loop does zero conversions.
// ---------------------------------------------------------------------------

#define Bb   4
#define Tt   2048
#define Hh   8
#define KVHh 2
#define BT   (Bb*Tt)      // 8192
#define EPSF 1e-6f

// ------------------------- scratch (device globals) ------------------------
__device__ float g_cq  [BT*256];
__device__ float g_qn  [BT*256];
__device__ float g_qr  [BT*256];
__device__ float g_ckv [BT*128];
__device__ float g_kn  [BT*64];
__device__ float g_kr  [BT*64];
__device__ float g_vraw[BT*128];
__device__ float g_vres[BT*512];
__device__ float g_q   [BT*512];              // [B,H,T,64] fp32
__device__ float g_ao  [BT*512];

// K/V in bf16 hi/lo, [B,KVH,T,64]
__device__ __nv_bfloat16 g_khi[Bb*KVHh*Tt*64];
__device__ __nv_bfloat16 g_klo[Bb*KVHh*Tt*64];
__device__ __nv_bfloat16 g_vhi[Bb*KVHh*Tt*64];
__device__ __nv_bfloat16 g_vlo[Bb*KVHh*Tt*64];

// activation split buffer (reused sequentially: x -> cq -> ckv -> ao)
__device__ __nv_bfloat16 g_ahi[BT*512];
__device__ __nv_bfloat16 g_alo[BT*512];

// transposed + bf16-split weights, [N][K] layout
#define OFF_DQ  0
#define OFF_UQ  131072
#define OFF_QR  196608
#define OFF_DKV 262144
#define OFF_UK  327680
#define OFF_UV  335872
#define OFF_KR  352256
#define OFF_VR  385024
#define OFF_WO  647168
#define WT_TOT  909312
__device__ __nv_bfloat16 g_whi[WT_TOT];
__device__ __nv_bfloat16 g_wlo[WT_TOT];

// ---------------------------------------------------------------------------
// mma.sync m16n8k16, row.col, bf16 x bf16 -> fp32   (layout verified in R6)
// ---------------------------------------------------------------------------
__device__ __forceinline__ void mma16816(
    float* d, const uint32_t* a, const uint32_t* b)
{
    asm volatile(
        "mma.sync.aligned.m16n8k16.row.col.f32.bf16.bf16.f32 "
        "{%0,%1,%2,%3}, {%4,%5,%6,%7}, {%8,%9}, {%0,%1,%2,%3};"
        : "+f"(d[0]), "+f"(d[1]), "+f"(d[2]), "+f"(d[3])
        : "r"(a[0]), "r"(a[1]), "r"(a[2]), "r"(a[3]), "r"(b[0]), "r"(b[1]));
}

__device__ __forceinline__ uint32_t pack_bf16(float lo, float hi) {
    __nv_bfloat162 p = __floats2bfloat162_rn(lo, hi);
    uint32_t u; memcpy(&u, &p, 4);
    return u;
}

// ---------------------------------------------------------------------------
// Transpose + bf16 hi/lo split: W[K][N] fp32 -> hi/lo [N][K] bf16.
// Grid (N/32, K/32), block (32,8).
// ---------------------------------------------------------------------------
__global__ void transpose_split(
    const float* __restrict__ W, __nv_bfloat16* __restrict__ hi,
    __nv_bfloat16* __restrict__ lo, int K, int N)
{
    __shared__ float t[32][33];
    const int k0 = blockIdx.y * 32, n0 = blockIdx.x * 32;
    for (int r = threadIdx.y; r < 32; r += 8)
        t[r][threadIdx.x] = W[(size_t)(k0 + r) * N + n0 + threadIdx.x];
    __syncthreads();
    for (int r = threadIdx.y; r < 32; r += 8) {
        float v = t[threadIdx.x][r];
        __nv_bfloat16 h = __float2bfloat16(v);
        __nv_bfloat16 l = __float2bfloat16(v - __bfloat162float(h));
        hi[(size_t)(n0 + r) * K + k0 + threadIdx.x] = h;
        lo[(size_t)(n0 + r) * K + k0 + threadIdx.x] = l;
    }
}

// ---------------------------------------------------------------------------
// Elementwise fp32 -> bf16 hi/lo split. nelem % 1024 == 0. Grid nelem/1024.
// ---------------------------------------------------------------------------
__global__ __launch_bounds__(256) void split_act(
    const float* __restrict__ x, __nv_bfloat16* __restrict__ hi,
    __nv_bfloat16* __restrict__ lo)
{
    const size_t job = (size_t)blockIdx.x * 256 + threadIdx.x;  // 4 floats/job
    float4 v = *(const float4*)(x + job * 4);
    float h0 = __bfloat162float(__float2bfloat16(v.x));
    float h1 = __bfloat162float(__float2bfloat16(v.y));
    float h2 = __bfloat162float(__float2bfloat16(v.z));
    float h3 = __bfloat162float(__float2bfloat16(v.w));
    uint2 ph = make_uint2(pack_bf16(h0, h1), pack_bf16(h2, h3));
    uint2 pl = make_uint2(pack_bf16(v.x - h0, v.y - h1), pack_bf16(v.z - h2, v.w - h3));
    *(uint2*)((uint32_t*)hi + job * 2) = ph;
    *(uint2*)((uint32_t*)lo + job * 2) = pl;
}

// ---------------------------------------------------------------------------
// HMMA GEMM, 3-term bf16 split: C[M,N] = A[M,K] * W^T  (W given as [N][K]).
// A pre-split bf16 hi/lo [M][K]; W pre-split bf16 hi/lo [N][K].
// Block: 256 threads = 8 warps; tile BM=128 (warp w: rows w*16..+15), BN.
// K-chunk 64. B staged in smem, stride 36 words (conflict-free, as in flash).
// ---------------------------------------------------------------------------
template <int BN>
__global__ __launch_bounds__(256) void hgemm(
    const __nv_bfloat16* __restrict__ Ahi, const __nv_bfloat16* __restrict__ Alo,
    const __nv_bfloat16* __restrict__ Whi, const __nv_bfloat16* __restrict__ Wlo,
    float* __restrict__ C, int M, int N, int K)
{
    __shared__ uint32_t sBhi[BN * 36];
    __shared__ uint32_t sBlo[BN * 36];

    const int bm = blockIdx.y * 128;
    const int bn = blockIdx.x * BN;
    const int tid = threadIdx.x;
    const int w = tid >> 5, lane = tid & 31;
    const int g = lane >> 2, t = lane & 3;
    constexpr int NT = BN / 8;

    float acc[NT][4];
    #pragma unroll
    for (int nt = 0; nt < NT; ++nt)
        #pragma unroll
        for (int j = 0; j < 4; ++j) acc[nt][j] = 0.f;

    const int r0 = bm + w * 16 + g;      // this thread's first A row

    const int nchunk = K >> 6;
    for (int ch = 0; ch < nchunk; ++ch) {
        __syncthreads();
        // ---- stage B chunk: BN rows x 64 k bf16 (hi+lo) ----
        #pragma unroll
        for (int j = tid; j < BN * 8; j += 256) {
            int n = j >> 3, c8 = j & 7;
            size_t go = (size_t)(bn + n) * K + ch * 64 + c8 * 8;
            *(uint4*)&sBhi[n * 36 + c8 * 4] = *(const uint4*)(Whi + go);
            *(uint4*)&sBlo[n * 36 + c8 * 4] = *(const uint4*)(Wlo + go);
        }
        __syncthreads();

        // ---- A fragments for this chunk (direct gmem, bf16 pre-split) ----
        uint32_t ahi[4][4], alo[4][4];
        {
            const size_t base0 = (size_t)r0 * K + ch * 64;
            const size_t base1 = base0 + 8 * (size_t)K;
            #pragma unroll
            for (int ks = 0; ks < 4; ++ks) {
                int c = ks * 16 + 2 * t;
                ahi[ks][0] = *(const uint32_t*)(Ahi + base0 + c);
                ahi[ks][1] = *(const uint32_t*)(Ahi + base1 + c);
                ahi[ks][2] = *(const uint32_t*)(Ahi + base0 + c + 8);
                ahi[ks][3] = *(const uint32_t*)(Ahi + base1 + c + 8);
                alo[ks][0] = *(const uint32_t*)(Alo + base0 + c);
                alo[ks][1] = *(const uint32_t*)(Alo + base1 + c);
                alo[ks][2] = *(const uint32_t*)(Alo + base0 + c + 8);
                alo[ks][3] = *(const uint32_t*)(Alo + base1 + c + 8);
            }
        }

        // ---- MMAs: 3 terms (AhiBhi + AloBhi + AhiBlo) ----
        #pragma unroll
        for (int nt = 0; nt < NT; ++nt) {
            const int nrow = nt * 8 + g;
            #pragma unroll
            for (int ks = 0; ks < 4; ++ks) {
                uint32_t bhi[2], blo[2];
                int base = nrow * 36 + ks * 8 + t;
                bhi[0] = sBhi[base]; bhi[1] = sBhi[base + 4];
                blo[0] = sBlo[base]; blo[1] = sBlo[base + 4];
                mma16816(acc[nt], ahi[ks], bhi);
                mma16816(acc[nt], alo[ks], bhi);
                mma16816(acc[nt], ahi[ks], blo);
            }
        }
    }

    // ---- epilogue ----
    #pragma unroll
    for (int nt = 0; nt < NT; ++nt) {
        const int col = bn + nt * 8 + 2 * t;
        *(float2*)(C + (size_t)r0 * N + col)       = make_float2(acc[nt][0], acc[nt][1]);
        *(float2*)(C + (size_t)(r0 + 8) * N + col) = make_float2(acc[nt][2], acc[nt][3]);
    }
}

// ---------------------------------------------------------------------------
// In-place RMSNorm over rows of length `dim`.
// ---------------------------------------------------------------------------
__global__ __launch_bounds__(128) void rms_inplace(
    float* __restrict__ x, const float* __restrict__ w, int dim)
{
    const int row = blockIdx.x;
    float* xr = x + (size_t)row * dim;
    float ss = 0.f;
    for (int i = threadIdx.x; i < dim; i += 128) { float v = xr[i]; ss += v * v; }
    #pragma unroll
    for (int off = 16; off; off >>= 1) ss += __shfl_xor_sync(0xffffffffu, ss, off);
    __shared__ float sred[4];
    if ((threadIdx.x & 31) == 0) sred[threadIdx.x >> 5] = ss;
    __syncthreads();
    float tot = sred[0] + sred[1] + sred[2] + sred[3];
    float rr = rsqrtf(tot / (float)dim + EPSF);
    for (int i = threadIdx.x; i < dim; i += 128) xr[i] = xr[i] * rr * w[i];
}

// ---------------------------------------------------------------------------
// Assemble: RoPE + concat + per-head RMSNorm; Q stays fp32 [B,H,T,64];
// K and V are emitted as bf16 hi/lo [B,KVH,T,64].
// ---------------------------------------------------------------------------
__global__ __launch_bounds__(256) void assemble(
    const float* __restrict__ qn, const float* __restrict__ qr,
    const float* __restrict__ kn, const float* __restrict__ kr,
    const float* __restrict__ vraw,
    const float* __restrict__ qhw, const float* __restrict__ khw,
    float* __restrict__ q,
    __nv_bfloat16* __restrict__ khi, __nv_bfloat16* __restrict__ klo,
    __nv_bfloat16* __restrict__ vhi, __nv_bfloat16* __restrict__ vlo)
{
    const int t = blockIdx.x, b = blockIdx.y;
    const int row = b * Tt + t;
    const int w = threadIdx.x >> 5, lane = threadIdx.x & 31;

    const int fi = lane & 15;
    float invf = (float)exp(-((double)fi / 16.0) * log(500000.0));
    float ph = (float)t * invf;
    float sv, cv;
    sincosf(ph, &sv, &cv);

    // ---- Q heads: warp w handles head h = w ----
    {
        const int h = w;
        const float* qnr = qn + (size_t)row * 256 + h * 32;
        const float* qrr = qr + (size_t)row * 256 + h * 32;
        float v0 = qnr[lane];
        float x1 = qrr[lane];
        float xr_ = (lane < 16) ? -qrr[lane + 16] : qrr[lane - 16];
        float v1 = x1 * cv + xr_ * sv;
        float ss = v0 * v0 + v1 * v1;
        #pragma unroll
        for (int off = 16; off; off >>= 1) ss += __shfl_xor_sync(0xffffffffu, ss, off);
        float rr = rsqrtf(ss / 64.0f + EPSF);
        float* qo = q + ((size_t)(b * Hh + h) * Tt + t) * 64;
        qo[lane]      = v0 * rr * qhw[lane];
        qo[lane + 32] = v1 * rr * qhw[lane + 32];
    }

    // ---- K heads: warps 0,1, emitted as bf16 hi/lo ----
    if (w < KVHh) {
        const int kvh = w;
        const float* knr = kn + (size_t)row * 64 + kvh * 32;
        const float* krr = kr + (size_t)row * 64 + kvh * 32;
        float v0 = knr[lane];
        float x1 = krr[lane];
        float xr_ = (lane < 16) ? -krr[lane + 16] : krr[lane - 16];
        float v1 = x1 * cv + xr_ * sv;
        float ss = v0 * v0 + v1 * v1;
        #pragma unroll
        for (int off = 16; off; off >>= 1) ss += __shfl_xor_sync(0xffffffffu, ss, off);
        float rr = rsqrtf(ss / 64.0f + EPSF);
        float k0 = v0 * rr * khw[lane];
        float k1 = v1 * rr * khw[lane + 32];
        size_t ko = ((size_t)(b * KVHh + kvh) * Tt + t) * 64;
        float h0 = __bfloat162float(__float2bfloat16(k0));
        float h1 = __bfloat162float(__float2bfloat16(k1));
        khi[ko + lane]      = __float2bfloat16(h0);
        khi[ko + lane + 32] = __float2bfloat16(h1);
        klo[ko + lane]      = __float2bfloat16(k0 - h0);
        klo[ko + lane + 32] = __float2bfloat16(k1 - h1);
    }

    // ---- V: split to bf16 hi/lo, [B,KVH,T,64] ----
    for (int i = threadIdx.x; i < 128; i += 256) {
        int kvh = i >> 6, d = i & 63;
        float val = vraw[(size_t)row * 128 + i];
        float h = __bfloat162float(__float2bfloat16(val));
        size_t o = ((size_t)(b * KVHh + kvh) * Tt + t) * 64 + d;
        vhi[o] = __float2bfloat16(h);
        vlo[o] = __float2bfloat16(val - h);
    }
}

// ---------------------------------------------------------------------------
// Flash attention on HMMA (verified R6 kernel); tile fill is now a pure
// bf16 copy (K/V pre-split by assemble). Grid (T/64, H, B), 128 threads.
// ---------------------------------------------------------------------------
__global__ __launch_bounds__(128) void flash_mma(
    const float* __restrict__ Q,
    const __nv_bfloat16* __restrict__ Khi, const __nv_bfloat16* __restrict__ Klo,
    const __nv_bfloat16* __restrict__ Vhi, const __nv_bfloat16* __restrict__ Vlo,
    const float* __restrict__ vres, float* __restrict__ out)
{
    __shared__ uint32_t sKhi[64 * 36];
    __shared__ uint32_t sKlo[64 * 36];
    __shared__ uint32_t sVhi[64 * 36];
    __shared__ uint32_t sVlo[64 * 36];

    const int qt = (Tt / 64 - 1) - blockIdx.x;   // heavy blocks first
    const int h = blockIdx.y, b = blockIdx.z;
    const int kvh = h >> 2;
    const float* qbase = Q + (((size_t)b * Hh + h) * Tt + qt * 64) * 64;
    const size_t kvbase = ((size_t)(b * KVHh + kvh) * Tt) * 64;

    const int tid  = threadIdx.x;
    const int w    = tid >> 5;
    const int lane = tid & 31;
    const int g    = lane >> 2;
    const int t    = lane & 3;

    // ---- Q fragments (built once), hi+lo split ----
    uint32_t qhi[4][4], qlo[4][4];
    {
        const float* r0 = qbase + (size_t)(w * 16 + g) * 64;
        const float* r1 = r0 + 8 * 64;
        #pragma unroll
        for (int ks = 0; ks < 4; ++ks) {
            float2 x0 = *(const float2*)(r0 + ks * 16 + 2 * t);
            float2 x1 = *(const float2*)(r1 + ks * 16 + 2 * t);
            float2 x2 = *(const float2*)(r0 + ks * 16 + 8 + 2 * t);
            float2 x3 = *(const float2*)(r1 + ks * 16 + 8 + 2 * t);
            float f[8] = {x0.x, x0.y, x1.x, x1.y, x2.x, x2.y, x3.x, x3.y};
            #pragma unroll
            for (int i = 0; i < 8; ++i) f[i] *= 0.125f;
            float hi[8], lo[8];
            #pragma unroll
            for (int i = 0; i < 8; ++i) {
                hi[i] = __bfloat162float(__float2bfloat16(f[i]));
                lo[i] = f[i] - hi[i];
            }
            #pragma unroll
            for (int r = 0; r < 4; ++r) {
                qhi[ks][r] = pack_bf16(hi[2*r], hi[2*r+1]);
                qlo[ks][r] = pack_bf16(lo[2*r], lo[2*r+1]);
            }
        }
    }

    float O[8][4];
    #pragma unroll
    for (int i = 0; i < 8; ++i)
        #pragma unroll
        for (int j = 0; j < 4; ++j) O[i][j] = 0.f;
    float mI[2] = {-3.0e38f, -3.0e38f};
    float lI[2] = {0.f, 0.f};

    for (int kt = 0; kt <= qt; ++kt) {
        const size_t tb = kvbase + (size_t)kt * 64 * 64;   // bf16 elements
        __syncthreads();
        // ---- fill K/V tiles: pure uint4 copies, stride-36-word layout ----
        #pragma unroll
        for (int it = 0; it < 4; ++it) {
            int idx = tid + it * 128;           // 0..511
            int row = idx >> 3, c8 = idx & 7;
            size_t go = tb + row * 64 + c8 * 8;
            int so = row * 36 + c8 * 4;
            *(uint4*)&sKhi[so] = *(const uint4*)(Khi + go);
            *(uint4*)&sKlo[so] = *(const uint4*)(Klo + go);
            *(uint4*)&sVhi[so] = *(const uint4*)(Vhi + go);
            *(uint4*)&sVlo[so] = *(const uint4*)(Vlo + go);
        }
        __syncthreads();

        // ---- S = Q K^T ----
        float S[8][4];
        #pragma unroll
        for (int nt = 0; nt < 8; ++nt) {
            float* sa = S[nt];
            sa[0] = sa[1] = sa[2] = sa[3] = 0.f;
            const int nrow = nt * 8 + g;
            #pragma unroll
            for (int ks = 0; ks < 4; ++ks) {
                uint32_t bhi[2], blo[2];
                int base = nrow * 36 + ks * 8 + t;
                bhi[0] = sKhi[base];     bhi[1] = sKhi[base + 4];
                blo[0] = sKlo[base];     blo[1] = sKlo[base + 4];
                mma16816(sa, qhi[ks], bhi);
                mma16816(sa, qlo[ks], bhi);
                mma16816(sa, qhi[ks], blo);
            }
        }

        if (kt == qt) {
            const int rg0 = w * 16 + g;
            #pragma unroll
            for (int nt = 0; nt < 8; ++nt) {
                int c0 = nt * 8 + 2 * t;
                if (c0 > rg0)     S[nt][0] = -1e30f;
                if (c0 + 1 > rg0) S[nt][1] = -1e30f;
                if (c0 > rg0 + 8)     S[nt][2] = -1e30f;
                if (c0 + 1 > rg0 + 8) S[nt][3] = -1e30f;
            }
        }

        // ---- online softmax ----
        float mt0 = -3.0e38f, mt1 = -3.0e38f;
        #pragma unroll
        for (int nt = 0; nt < 8; ++nt) {
            mt0 = fmaxf(mt0, fmaxf(S[nt][0], S[nt][1]));
            mt1 = fmaxf(mt1, fmaxf(S[nt][2], S[nt][3]));
        }
        mt0 = fmaxf(mt0, __shfl_xor_sync(0xffffffffu, mt0, 1));
        mt0 = fmaxf(mt0, __shfl_xor_sync(0xffffffffu, mt0, 2));
        mt1 = fmaxf(mt1, __shfl_xor_sync(0xffffffffu, mt1, 1));
        mt1 = fmaxf(mt1, __shfl_xor_sync(0xffffffffu, mt1, 2));
        float mn0 = fmaxf(mI[0], mt0), mn1 = fmaxf(mI[1], mt1);
        float al0 = __expf(mI[0] - mn0), al1 = __expf(mI[1] - mn1);
        mI[0] = mn0; mI[1] = mn1;

        float sum0 = 0.f, sum1 = 0.f;
        #pragma unroll
        for (int nt = 0; nt < 8; ++nt) {
            S[nt][0] = __expf(S[nt][0] - mn0); sum0 += S[nt][0];
            S[nt][1] = __expf(S[nt][1] - mn0); sum0 += S[nt][1];
            S[nt][2] = __expf(S[nt][2] - mn1); sum1 += S[nt][2];
            S[nt][3] = __expf(S[nt][3] - mn1); sum1 += S[nt][3];
        }
        sum0 += __shfl_xor_sync(0xffffffffu, sum0, 1);
        sum0 += __shfl_xor_sync(0xffffffffu, sum0, 2);
        sum1 += __shfl_xor_sync(0xffffffffu, sum1, 1);
        sum1 += __shfl_xor_sync(0xffffffffu, sum1, 2);
        lI[0] = lI[0] * al0 + sum0;
        lI[1] = lI[1] * al1 + sum1;
        #pragma unroll
        for (int dt = 0; dt < 8; ++dt) {
            O[dt][0] *= al0; O[dt][1] *= al0;
            O[dt][2] *= al1; O[dt][3] *= al1;
        }

        // ---- P fragments (C-frag -> A-frag identity), hi/lo split ----
        uint32_t phi[8][2], plo[8][2];
        #pragma unroll
        for (int nt = 0; nt < 8; ++nt) {
            float h0 = __bfloat162float(__float2bfloat16(S[nt][0]));
            float h1 = __bfloat162float(__float2bfloat16(S[nt][1]));
            float h2 = __bfloat162float(__float2bfloat16(S[nt][2]));
            float h3 = __bfloat162float(__float2bfloat16(S[nt][3]));
            phi[nt][0] = pack_bf16(h0, h1);
            phi[nt][1] = pack_bf16(h2, h3);
            plo[nt][0] = pack_bf16(S[nt][0] - h0, S[nt][1] - h1);
            plo[nt][1] = pack_bf16(S[nt][2] - h2, S[nt][3] - h3);
        }

        // ---- O += P V ----
        #pragma unroll
        for (int ks = 0; ks < 4; ++ks) {
            uint32_t aP[4] = {phi[2*ks][0], phi[2*ks][1], phi[2*ks+1][0], phi[2*ks+1][1]};
            uint32_t aL[4] = {plo[2*ks][0], plo[2*ks][1], plo[2*ks+1][0], plo[2*ks+1][1]};
            const int r0 = ks * 16 + 2 * t;
            #pragma unroll
            for (int dt = 0; dt < 8; ++dt) {
                const int n = dt * 8 + g;
                const __nv_bfloat16* vh = (const __nv_bfloat16*)sVhi;
                const __nv_bfloat16* vl = (const __nv_bfloat16*)sVlo;
                uint32_t bhi[2], blo[2];
                bhi[0] = pack_bf16(__bfloat162float(vh[(r0    ) * 72 + n]),
                                   __bfloat162float(vh[(r0 + 1) * 72 + n]));
                bhi[1] = pack_bf16(__bfloat162float(vh[(r0 + 8) * 72 + n]),
                                   __bfloat162float(vh[(r0 + 9) * 72 + n]));
                blo[0] = pack_bf16(__bfloat162float(vl[(r0    ) * 72 + n]),
                                   __bfloat162float(vl[(r0 + 1) * 72 + n]));
                blo[1] = pack_bf16(__bfloat162float(vl[(r0 + 8) * 72 + n]),
                                   __bfloat162float(vl[(r0 + 9) * 72 + n]));
                mma16816(O[dt], aP, bhi);
                mma16816(O[dt], aL, bhi);
                mma16816(O[dt], aP, blo);
            }
        }
    }

    // ---- epilogue ----
    const float inv0 = 1.0f / lI[0];
    const float inv1 = 1.0f / lI[1];
    const size_t row0 = (size_t)b * Tt + qt * 64 + w * 16 + g;
    const size_t row1 = row0 + 8;
    #pragma unroll
    for (int dt = 0; dt < 8; ++dt) {
        const int col = h * 64 + dt * 8 + 2 * t;
        float2 vr0 = *(const float2*)(vres + row0 * 512 + col);
        float2 vr1 = *(const float2*)(vres + row1 * 512 + col);
        float2 o0 = make_float2(O[dt][0] * inv0 + vr0.x, O[dt][1] * inv0 + vr0.y);
        float2 o1 = make_float2(O[dt][2] * inv1 + vr1.x, O[dt][3] * inv1 + vr1.y);
        *(float2*)(out + row0 * 512 + col) = o0;
        *(float2*)(out + row1 * 512 + col) = o1;
    }
}

// ---------------------------------------------------------------------------
extern "C" void kernel_launch(void* const* d_in, const int* in_sizes, int n_in,
                              void* d_out, int out_size)
{
    const float* x    = (const float*)d_in[0];
    const float* WDQ  = (const float*)d_in[1];
    const float* WUQ  = (const float*)d_in[2];
    const float* WQR  = (const float*)d_in[3];
    const float* WDKV = (const float*)d_in[4];
    const float* WUK  = (const float*)d_in[5];
    const float* WUV  = (const float*)d_in[6];
    const float* WKR  = (const float*)d_in[7];
    const float* WVR  = (const float*)d_in[8];
    const float* WO   = (const float*)d_in[9];
    const float* qlnw = (const float*)d_in[10];
    const float* kvlnw= (const float*)d_in[11];
    const float* qhw  = (const float*)d_in[12];
    const float* khw  = (const float*)d_in[13];
    float* out = (float*)d_out;

    float *cq, *qn, *qr, *ckv, *kn, *kr, *vraw, *vres, *q, *ao;
    __nv_bfloat16 *khi, *klo, *vhi, *vlo, *ahi, *alo, *whi, *wlo;
    cudaGetSymbolAddress((void**)&cq,   g_cq);
    cudaGetSymbolAddress((void**)&qn,   g_qn);
    cudaGetSymbolAddress((void**)&qr,   g_qr);
    cudaGetSymbolAddress((void**)&ckv,  g_ckv);
    cudaGetSymbolAddress((void**)&kn,   g_kn);
    cudaGetSymbolAddress((void**)&kr,   g_kr);
    cudaGetSymbolAddress((void**)&vraw, g_vraw);
    cudaGetSymbolAddress((void**)&vres, g_vres);
    cudaGetSymbolAddress((void**)&q,    g_q);
    cudaGetSymbolAddress((void**)&ao,   g_ao);
    cudaGetSymbolAddress((void**)&khi,  g_khi);
    cudaGetSymbolAddress((void**)&klo,  g_klo);
    cudaGetSymbolAddress((void**)&vhi,  g_vhi);
    cudaGetSymbolAddress((void**)&vlo,  g_vlo);
    cudaGetSymbolAddress((void**)&ahi,  g_ahi);
    cudaGetSymbolAddress((void**)&alo,  g_alo);
    cudaGetSymbolAddress((void**)&whi,  g_whi);
    cudaGetSymbolAddress((void**)&wlo,  g_wlo);

    // ---- weights: transpose + split once ----
    dim3 tb(32, 8);
    transpose_split<<<dim3(256/32, 512/32), tb>>>(WDQ,  whi + OFF_DQ,  wlo + OFF_DQ,  512, 256);
    transpose_split<<<dim3(256/32, 256/32), tb>>>(WUQ,  whi + OFF_UQ,  wlo + OFF_UQ,  256, 256);
    transpose_split<<<dim3(256/32, 256/32), tb>>>(WQR,  whi + OFF_QR,  wlo + OFF_QR,  256, 256);
    transpose_split<<<dim3(128/32, 512/32), tb>>>(WDKV, whi + OFF_DKV, wlo + OFF_DKV, 512, 128);
    transpose_split<<<dim3(64/32,  128/32), tb>>>(WUK,  whi + OFF_UK,  wlo + OFF_UK,  128, 64);
    transpose_split<<<dim3(128/32, 128/32), tb>>>(WUV,  whi + OFF_UV,  wlo + OFF_UV,  128, 128);
    transpose_split<<<dim3(64/32,  512/32), tb>>>(WKR,  whi + OFF_KR,  wlo + OFF_KR,  512, 64);
    transpose_split<<<dim3(512/32, 512/32), tb>>>(WVR,  whi + OFF_VR,  wlo + OFF_VR,  512, 512);
    transpose_split<<<dim3(512/32, 512/32), tb>>>(WO,   whi + OFF_WO,  wlo + OFF_WO,  512, 512);

    // ---- x-split, then all GEMMs that consume x ----
    split_act<<<BT*512/1024, 256>>>(x, ahi, alo);
    hgemm<128><<<dim3(2, 64), 256>>>(ahi, alo, whi + OFF_DQ,  wlo + OFF_DQ,  cq,   BT, 256, 512);
    hgemm<128><<<dim3(1, 64), 256>>>(ahi, alo, whi + OFF_DKV, wlo + OFF_DKV, ckv,  BT, 128, 512);
    hgemm<64> <<<dim3(1, 64), 256>>>(ahi, alo, whi + OFF_KR,  wlo + OFF_KR,  kr,   BT, 64,  512);
    hgemm<128><<<dim3(4, 64), 256>>>(ahi, alo, whi + OFF_VR,  wlo + OFF_VR,  vres, BT, 512, 512);

    // ---- Q path ----
    rms_inplace<<<BT, 128>>>(cq, qlnw, 256);
    split_act<<<BT*256/1024, 256>>>(cq, ahi, alo);
    hgemm<128><<<dim3(2, 64), 256>>>(ahi, alo, whi + OFF_UQ, wlo + OFF_UQ, qn, BT, 256, 256);
    hgemm<128><<<dim3(2, 64), 256>>>(ahi, alo, whi + OFF_QR, wlo + OFF_QR, qr, BT, 256, 256);

    // ---- KV path ----
    rms_inplace<<<BT, 128>>>(ckv, kvlnw, 128);
    split_act<<<BT*128/1024, 256>>>(ckv, ahi, alo);
    hgemm<64> <<<dim3(1, 64), 256>>>(ahi, alo, whi + OFF_UK, wlo + OFF_UK, kn,   BT, 64,  128);
    hgemm<128><<<dim3(1, 64), 256>>>(ahi, alo, whi + OFF_UV, wlo + OFF_UV, vraw, BT, 128, 128);

    // ---- rope + head-norm + layout (K/V emitted as bf16 hi/lo) ----
    assemble<<<dim3(Tt, Bb), 256>>>(qn, qr, kn, kr, vraw, qhw, khw,
                                    q, khi, klo, vhi, vlo);
    // ---- causal flash attention (+ residual add) ----
    flash_mma<<<dim3(Tt/64, Hh, Bb), 128>>>(q, khi, klo, vhi, vlo, vres, ao);
    // ---- output projection ----
    split_act<<<BT*512/1024, 256>>>(ao, ahi, alo);
    hgemm<128><<<dim3(4, 64), 256>>>(ahi, alo, whi + OFF_WO, wlo + OFF_WO, out, BT, 512, 512);
}

// round 8
// speedup vs baseline: 2.6216x; 1.1895x over previous
#include <cuda_runtime.h>
#include <cuda_bf16.h>
#include <math.h>
#include <cstdint>
#include <cstring>

// ---------------------------------------------------------------------------
// MLA attention pipeline. B=4, T=2048, D=512, H=8, KVH=2, HD=64
// Round 8: ldmatrix for all MMA B-fragments (x4 for K/W, x4.trans for V),
// register-prefetch double buffering in hgemm, batched weight transpose.
// ---------------------------------------------------------------------------

#define Bb   4
#define Tt   2048
#define Hh   8
#define KVHh 2
#define BT   (Bb*Tt)      // 8192
#define EPSF 1e-6f

// ------------------------- scratch (device globals) ------------------------
__device__ float g_cq  [BT*256];
__device__ float g_qn  [BT*256];
__device__ float g_qr  [BT*256];
__device__ float g_ckv [BT*128];
__device__ float g_kn  [BT*64];
__device__ float g_kr  [BT*64];
__device__ float g_vraw[BT*128];
__device__ float g_vres[BT*512];
__device__ float g_q   [BT*512];              // [B,H,T,64] fp32
__device__ float g_ao  [BT*512];

__device__ __nv_bfloat16 g_khi[Bb*KVHh*Tt*64];
__device__ __nv_bfloat16 g_klo[Bb*KVHh*Tt*64];
__device__ __nv_bfloat16 g_vhi[Bb*KVHh*Tt*64];
__device__ __nv_bfloat16 g_vlo[Bb*KVHh*Tt*64];

__device__ __nv_bfloat16 g_ahi[BT*512];
__device__ __nv_bfloat16 g_alo[BT*512];

// transposed + bf16-split weights, [N][K] layout
#define OFF_DQ  0
#define OFF_UQ  131072
#define OFF_QR  196608
#define OFF_DKV 262144
#define OFF_UK  327680
#define OFF_UV  335872
#define OFF_KR  352256
#define OFF_VR  385024
#define OFF_WO  647168
#define WT_TOT  909312
__device__ __nv_bfloat16 g_whi[WT_TOT];
__device__ __nv_bfloat16 g_wlo[WT_TOT];

// ------------------------- PTX helpers -------------------------------------
__device__ __forceinline__ void mma16816(
    float* d, const uint32_t* a, const uint32_t* b)
{
    asm volatile(
        "mma.sync.aligned.m16n8k16.row.col.f32.bf16.bf16.f32 "
        "{%0,%1,%2,%3}, {%4,%5,%6,%7}, {%8,%9}, {%0,%1,%2,%3};"
        : "+f"(d[0]), "+f"(d[1]), "+f"(d[2]), "+f"(d[3])
        : "r"(a[0]), "r"(a[1]), "r"(a[2]), "r"(a[3]), "r"(b[0]), "r"(b[1]));
}

__device__ __forceinline__ void ldsm4(uint32_t* r, uint32_t addr) {
    asm volatile("ldmatrix.sync.aligned.m8n8.x4.shared.b16 {%0,%1,%2,%3}, [%4];"
        : "=r"(r[0]), "=r"(r[1]), "=r"(r[2]), "=r"(r[3]) : "r"(addr));
}
__device__ __forceinline__ void ldsm4t(uint32_t* r, uint32_t addr) {
    asm volatile("ldmatrix.sync.aligned.m8n8.x4.trans.shared.b16 {%0,%1,%2,%3}, [%4];"
        : "=r"(r[0]), "=r"(r[1]), "=r"(r[2]), "=r"(r[3]) : "r"(addr));
}

__device__ __forceinline__ uint32_t smem_u32(const void* p) {
    uint32_t a;
    asm("{ .reg .u64 t; cvta.to.shared.u64 t, %1; cvt.u32.u64 %0, t; }"
        : "=r"(a) : "l"(p));
    return a;
}

__device__ __forceinline__ uint32_t pack_bf16(float lo, float hi) {
    __nv_bfloat162 p = __floats2bfloat162_rn(lo, hi);
    uint32_t u; memcpy(&u, &p, 4);
    return u;
}

// ---------------------------------------------------------------------------
// Batched transpose + bf16 hi/lo split: 9 weights in one launch.
// W[K][N] fp32 -> hi/lo [N][K] bf16 at whi/wlo + woff.
// ---------------------------------------------------------------------------
struct TJobs {
    const float* W[9];
    int K[9], N[9], woff[9];
    int t0[10];   // tile prefix sums; t0[9] = total tiles
};

__global__ void transpose_split_all(
    TJobs jb, __nv_bfloat16* __restrict__ hi, __nv_bfloat16* __restrict__ lo)
{
    __shared__ float t[32][33];
    const int bid = blockIdx.x;
    int j = 0;
    #pragma unroll
    for (int i = 0; i < 8; ++i) if (bid >= jb.t0[i + 1]) j = i + 1;
    const int tile = bid - jb.t0[j];
    const int K = jb.K[j], N = jb.N[j];
    const int ntx = N / 32;
    const int n0 = (tile % ntx) * 32, k0 = (tile / ntx) * 32;
    const float* W = jb.W[j];
    __nv_bfloat16* ho = hi + jb.woff[j];
    __nv_bfloat16* lp = lo + jb.woff[j];

    for (int r = threadIdx.y; r < 32; r += 8)
        t[r][threadIdx.x] = W[(size_t)(k0 + r) * N + n0 + threadIdx.x];
    __syncthreads();
    for (int r = threadIdx.y; r < 32; r += 8) {
        float v = t[threadIdx.x][r];
        __nv_bfloat16 h = __float2bfloat16(v);
        __nv_bfloat16 l = __float2bfloat16(v - __bfloat162float(h));
        ho[(size_t)(n0 + r) * K + k0 + threadIdx.x] = h;
        lp[(size_t)(n0 + r) * K + k0 + threadIdx.x] = l;
    }
}

// ---------------------------------------------------------------------------
// Elementwise fp32 -> bf16 hi/lo split.
// ---------------------------------------------------------------------------
__global__ __launch_bounds__(256) void split_act(
    const float* __restrict__ x, __nv_bfloat16* __restrict__ hi,
    __nv_bfloat16* __restrict__ lo)
{
    const size_t job = (size_t)blockIdx.x * 256 + threadIdx.x;
    float4 v = *(const float4*)(x + job * 4);
    float h0 = __bfloat162float(__float2bfloat16(v.x));
    float h1 = __bfloat162float(__float2bfloat16(v.y));
    float h2 = __bfloat162float(__float2bfloat16(v.z));
    float h3 = __bfloat162float(__float2bfloat16(v.w));
    uint2 ph = make_uint2(pack_bf16(h0, h1), pack_bf16(h2, h3));
    uint2 pl = make_uint2(pack_bf16(v.x - h0, v.y - h1), pack_bf16(v.z - h2, v.w - h3));
    *(uint2*)((uint32_t*)hi + job * 2) = ph;
    *(uint2*)((uint32_t*)lo + job * 2) = pl;
}

// ---------------------------------------------------------------------------
// HMMA GEMM, 3-term bf16 split, ldmatrix B-frags, register-prefetched B.
// C[M,N] = A * W^T.  A hi/lo [M][K]; W hi/lo [N][K]. 256 thr, BM=128.
// ---------------------------------------------------------------------------
template <int BN>
__global__ __launch_bounds__(256) void hgemm(
    const __nv_bfloat16* __restrict__ Ahi, const __nv_bfloat16* __restrict__ Alo,
    const __nv_bfloat16* __restrict__ Whi, const __nv_bfloat16* __restrict__ Wlo,
    float* __restrict__ C, int M, int N, int K)
{
    __shared__ uint32_t sBhi[BN * 36];
    __shared__ uint32_t sBlo[BN * 36];

    const int bm = blockIdx.y * 128;
    const int bn = blockIdx.x * BN;
    const int tid = threadIdx.x;
    const int w = tid >> 5, lane = tid & 31;
    const int g = lane >> 2, t = lane & 3;
    constexpr int NT = BN / 8;
    constexpr int NJ = BN / 32;          // uint4 jobs per thread

    const uint32_t bH = smem_u32(sBhi);
    const uint32_t bL = smem_u32(sBlo);
    const int lrow = (lane & 7) * 36;    // ldmatrix row part (words)
    const int lm   = (lane >> 3) * 4;    // ldmatrix matrix part (words)

    float acc[NT][4];
    #pragma unroll
    for (int nt = 0; nt < NT; ++nt)
        #pragma unroll
        for (int j = 0; j < 4; ++j) acc[nt][j] = 0.f;

    const int r0 = bm + w * 16 + g;

    int jn[NJ], jc[NJ];
    #pragma unroll
    for (int i = 0; i < NJ; ++i) { int j = tid + i * 256; jn[i] = j >> 3; jc[i] = j & 7; }

    uint4 pfh[NJ], pfl[NJ];
    #pragma unroll
    for (int i = 0; i < NJ; ++i) {
        size_t go = (size_t)(bn + jn[i]) * K + jc[i] * 8;
        pfh[i] = *(const uint4*)(Whi + go);
        pfl[i] = *(const uint4*)(Wlo + go);
    }

    const int nchunk = K >> 6;
    for (int ch = 0; ch < nchunk; ++ch) {
        __syncthreads();
        #pragma unroll
        for (int i = 0; i < NJ; ++i) {
            *(uint4*)&sBhi[jn[i] * 36 + jc[i] * 4] = pfh[i];
            *(uint4*)&sBlo[jn[i] * 36 + jc[i] * 4] = pfl[i];
        }
        __syncthreads();
        if (ch + 1 < nchunk) {
            #pragma unroll
            for (int i = 0; i < NJ; ++i) {
                size_t go = (size_t)(bn + jn[i]) * K + (ch + 1) * 64 + jc[i] * 8;
                pfh[i] = *(const uint4*)(Whi + go);
                pfl[i] = *(const uint4*)(Wlo + go);
            }
        }

        // A fragments (gmem, bf16 pre-split)
        uint32_t ahi[4][4], alo[4][4];
        {
            const size_t base0 = (size_t)r0 * K + ch * 64;
            const size_t base1 = base0 + 8 * (size_t)K;
            #pragma unroll
            for (int ks = 0; ks < 4; ++ks) {
                int c = ks * 16 + 2 * t;
                ahi[ks][0] = *(const uint32_t*)(Ahi + base0 + c);
                ahi[ks][1] = *(const uint32_t*)(Ahi + base1 + c);
                ahi[ks][2] = *(const uint32_t*)(Ahi + base0 + c + 8);
                ahi[ks][3] = *(const uint32_t*)(Ahi + base1 + c + 8);
                alo[ks][0] = *(const uint32_t*)(Alo + base0 + c);
                alo[ks][1] = *(const uint32_t*)(Alo + base1 + c);
                alo[ks][2] = *(const uint32_t*)(Alo + base0 + c + 8);
                alo[ks][3] = *(const uint32_t*)(Alo + base1 + c + 8);
            }
        }

        #pragma unroll
        for (int nt = 0; nt < NT; ++nt) {
            uint32_t bh[8], bl[8];
            const int wo = nt * 288 + lrow + lm;
            ldsm4(bh,     bH + wo * 4);
            ldsm4(bh + 4, bH + (wo + 16) * 4);
            ldsm4(bl,     bL + wo * 4);
            ldsm4(bl + 4, bL + (wo + 16) * 4);
            #pragma unroll
            for (int ks = 0; ks < 4; ++ks) {
                mma16816(acc[nt], ahi[ks], bh + 2 * ks);
                mma16816(acc[nt], alo[ks], bh + 2 * ks);
                mma16816(acc[nt], ahi[ks], bl + 2 * ks);
            }
        }
    }

    #pragma unroll
    for (int nt = 0; nt < NT; ++nt) {
        const int col = bn + nt * 8 + 2 * t;
        *(float2*)(C + (size_t)r0 * N + col)       = make_float2(acc[nt][0], acc[nt][1]);
        *(float2*)(C + (size_t)(r0 + 8) * N + col) = make_float2(acc[nt][2], acc[nt][3]);
    }
}

// ---------------------------------------------------------------------------
// In-place RMSNorm over rows of length `dim`.
// ---------------------------------------------------------------------------
__global__ __launch_bounds__(128) void rms_inplace(
    float* __restrict__ x, const float* __restrict__ w, int dim)
{
    const int row = blockIdx.x;
    float* xr = x + (size_t)row * dim;
    float ss = 0.f;
    for (int i = threadIdx.x; i < dim; i += 128) { float v = xr[i]; ss += v * v; }
    #pragma unroll
    for (int off = 16; off; off >>= 1) ss += __shfl_xor_sync(0xffffffffu, ss, off);
    __shared__ float sred[4];
    if ((threadIdx.x & 31) == 0) sred[threadIdx.x >> 5] = ss;
    __syncthreads();
    float tot = sred[0] + sred[1] + sred[2] + sred[3];
    float rr = rsqrtf(tot / (float)dim + EPSF);
    for (int i = threadIdx.x; i < dim; i += 128) xr[i] = xr[i] * rr * w[i];
}

// ---------------------------------------------------------------------------
// Assemble: RoPE + concat + per-head RMSNorm; Q fp32; K/V bf16 hi/lo.
// ---------------------------------------------------------------------------
__global__ __launch_bounds__(256) void assemble(
    const float* __restrict__ qn, const float* __restrict__ qr,
    const float* __restrict__ kn, const float* __restrict__ kr,
    const float* __restrict__ vraw,
    const float* __restrict__ qhw, const float* __restrict__ khw,
    float* __restrict__ q,
    __nv_bfloat16* __restrict__ khi, __nv_bfloat16* __restrict__ klo,
    __nv_bfloat16* __restrict__ vhi, __nv_bfloat16* __restrict__ vlo)
{
    const int t = blockIdx.x, b = blockIdx.y;
    const int row = b * Tt + t;
    const int w = threadIdx.x >> 5, lane = threadIdx.x & 31;

    const int fi = lane & 15;
    float invf = (float)exp(-((double)fi / 16.0) * log(500000.0));
    float ph = (float)t * invf;
    float sv, cv;
    sincosf(ph, &sv, &cv);

    {
        const int h = w;
        const float* qnr = qn + (size_t)row * 256 + h * 32;
        const float* qrr = qr + (size_t)row * 256 + h * 32;
        float v0 = qnr[lane];
        float x1 = qrr[lane];
        float xr_ = (lane < 16) ? -qrr[lane + 16] : qrr[lane - 16];
        float v1 = x1 * cv + xr_ * sv;
        float ss = v0 * v0 + v1 * v1;
        #pragma unroll
        for (int off = 16; off; off >>= 1) ss += __shfl_xor_sync(0xffffffffu, ss, off);
        float rr = rsqrtf(ss / 64.0f + EPSF);
        float* qo = q + ((size_t)(b * Hh + h) * Tt + t) * 64;
        qo[lane]      = v0 * rr * qhw[lane];
        qo[lane + 32] = v1 * rr * qhw[lane + 32];
    }

    if (w < KVHh) {
        const int kvh = w;
        const float* knr = kn + (size_t)row * 64 + kvh * 32;
        const float* krr = kr + (size_t)row * 64 + kvh * 32;
        float v0 = knr[lane];
        float x1 = krr[lane];
        float xr_ = (lane < 16) ? -krr[lane + 16] : krr[lane - 16];
        float v1 = x1 * cv + xr_ * sv;
        float ss = v0 * v0 + v1 * v1;
        #pragma unroll
        for (int off = 16; off; off >>= 1) ss += __shfl_xor_sync(0xffffffffu, ss, off);
        float rr = rsqrtf(ss / 64.0f + EPSF);
        float k0 = v0 * rr * khw[lane];
        float k1 = v1 * rr * khw[lane + 32];
        size_t ko = ((size_t)(b * KVHh + kvh) * Tt + t) * 64;
        float h0 = __bfloat162float(__float2bfloat16(k0));
        float h1 = __bfloat162float(__float2bfloat16(k1));
        khi[ko + lane]      = __float2bfloat16(h0);
        khi[ko + lane + 32] = __float2bfloat16(h1);
        klo[ko + lane]      = __float2bfloat16(k0 - h0);
        klo[ko + lane + 32] = __float2bfloat16(k1 - h1);
    }

    for (int i = threadIdx.x; i < 128; i += 256) {
        int kvh = i >> 6, d = i & 63;
        float val = vraw[(size_t)row * 128 + i];
        float h = __bfloat162float(__float2bfloat16(val));
        size_t o = ((size_t)(b * KVHh + kvh) * Tt + t) * 64 + d;
        vhi[o] = __float2bfloat16(h);
        vlo[o] = __float2bfloat16(val - h);
    }
}

// ---------------------------------------------------------------------------
// Flash attention on HMMA, ldmatrix fragment loads. Grid (T/64, H, B), 128 thr.
// ---------------------------------------------------------------------------
__global__ __launch_bounds__(128) void flash_mma(
    const float* __restrict__ Q,
    const __nv_bfloat16* __restrict__ Khi, const __nv_bfloat16* __restrict__ Klo,
    const __nv_bfloat16* __restrict__ Vhi, const __nv_bfloat16* __restrict__ Vlo,
    const float* __restrict__ vres, float* __restrict__ out)
{
    __shared__ uint32_t sKhi[64 * 36];
    __shared__ uint32_t sKlo[64 * 36];
    __shared__ uint32_t sVhi[64 * 36];
    __shared__ uint32_t sVlo[64 * 36];

    const int qt = (Tt / 64 - 1) - blockIdx.x;   // heavy blocks first
    const int h = blockIdx.y, b = blockIdx.z;
    const int kvh = h >> 2;
    const float* qbase = Q + (((size_t)b * Hh + h) * Tt + qt * 64) * 64;
    const size_t kvbase = ((size_t)(b * KVHh + kvh) * Tt) * 64;

    const int tid  = threadIdx.x;
    const int w    = tid >> 5;
    const int lane = tid & 31;
    const int g    = lane >> 2;
    const int t    = lane & 3;

    const uint32_t kH = smem_u32(sKhi), kL = smem_u32(sKlo);
    const uint32_t vH = smem_u32(sVhi), vL = smem_u32(sVlo);
    const int lrow = (lane & 7) * 36;                       // K frag row part
    const int lm   = (lane >> 3) * 4;                       // K frag matrix part
    const int vrow = (((lane >> 3) & 1) * 8 + (lane & 7)) * 36;  // V trans row part
    const int vd   = (lane >> 4) * 4;                       // V trans d part

    // ---- Q fragments (built once), hi+lo split ----
    uint32_t qhi[4][4], qlo[4][4];
    {
        const float* r0 = qbase + (size_t)(w * 16 + g) * 64;
        const float* r1 = r0 + 8 * 64;
        #pragma unroll
        for (int ks = 0; ks < 4; ++ks) {
            float2 x0 = *(const float2*)(r0 + ks * 16 + 2 * t);
            float2 x1 = *(const float2*)(r1 + ks * 16 + 2 * t);
            float2 x2 = *(const float2*)(r0 + ks * 16 + 8 + 2 * t);
            float2 x3 = *(const float2*)(r1 + ks * 16 + 8 + 2 * t);
            float f[8] = {x0.x, x0.y, x1.x, x1.y, x2.x, x2.y, x3.x, x3.y};
            #pragma unroll
            for (int i = 0; i < 8; ++i) f[i] *= 0.125f;
            float hi[8], lo[8];
            #pragma unroll
            for (int i = 0; i < 8; ++i) {
                hi[i] = __bfloat162float(__float2bfloat16(f[i]));
                lo[i] = f[i] - hi[i];
            }
            #pragma unroll
            for (int r = 0; r < 4; ++r) {
                qhi[ks][r] = pack_bf16(hi[2*r], hi[2*r+1]);
                qlo[ks][r] = pack_bf16(lo[2*r], lo[2*r+1]);
            }
        }
    }

    float O[8][4];
    #pragma unroll
    for (int i = 0; i < 8; ++i)
        #pragma unroll
        for (int j = 0; j < 4; ++j) O[i][j] = 0.f;
    float mI[2] = {-3.0e38f, -3.0e38f};
    float lI[2] = {0.f, 0.f};

    for (int kt = 0; kt <= qt; ++kt) {
        const size_t tb = kvbase + (size_t)kt * 64 * 64;
        __syncthreads();
        #pragma unroll
        for (int it = 0; it < 4; ++it) {
            int idx = tid + it * 128;
            int row = idx >> 3, c8 = idx & 7;
            size_t go = tb + row * 64 + c8 * 8;
            int so = row * 36 + c8 * 4;
            *(uint4*)&sKhi[so] = *(const uint4*)(Khi + go);
            *(uint4*)&sKlo[so] = *(const uint4*)(Klo + go);
            *(uint4*)&sVhi[so] = *(const uint4*)(Vhi + go);
            *(uint4*)&sVlo[so] = *(const uint4*)(Vlo + go);
        }
        __syncthreads();

        // ---- S = Q K^T (K frags via ldmatrix.x4) ----
        float S[8][4];
        #pragma unroll
        for (int nt = 0; nt < 8; ++nt) {
            float* sa = S[nt];
            sa[0] = sa[1] = sa[2] = sa[3] = 0.f;
            uint32_t bh[8], bl[8];
            const int wo = nt * 288 + lrow + lm;
            ldsm4(bh,     kH + wo * 4);
            ldsm4(bh + 4, kH + (wo + 16) * 4);
            ldsm4(bl,     kL + wo * 4);
            ldsm4(bl + 4, kL + (wo + 16) * 4);
            #pragma unroll
            for (int ks = 0; ks < 4; ++ks) {
                mma16816(sa, qhi[ks], bh + 2 * ks);
                mma16816(sa, qlo[ks], bh + 2 * ks);
                mma16816(sa, qhi[ks], bl + 2 * ks);
            }
        }

        if (kt == qt) {
            const int rg0 = w * 16 + g;
            #pragma unroll
            for (int nt = 0; nt < 8; ++nt) {
                int c0 = nt * 8 + 2 * t;
                if (c0 > rg0)     S[nt][0] = -1e30f;
                if (c0 + 1 > rg0) S[nt][1] = -1e30f;
                if (c0 > rg0 + 8)     S[nt][2] = -1e30f;
                if (c0 + 1 > rg0 + 8) S[nt][3] = -1e30f;
            }
        }

        // ---- online softmax ----
        float mt0 = -3.0e38f, mt1 = -3.0e38f;
        #pragma unroll
        for (int nt = 0; nt < 8; ++nt) {
            mt0 = fmaxf(mt0, fmaxf(S[nt][0], S[nt][1]));
            mt1 = fmaxf(mt1, fmaxf(S[nt][2], S[nt][3]));
        }
        mt0 = fmaxf(mt0, __shfl_xor_sync(0xffffffffu, mt0, 1));
        mt0 = fmaxf(mt0, __shfl_xor_sync(0xffffffffu, mt0, 2));
        mt1 = fmaxf(mt1, __shfl_xor_sync(0xffffffffu, mt1, 1));
        mt1 = fmaxf(mt1, __shfl_xor_sync(0xffffffffu, mt1, 2));
        float mn0 = fmaxf(mI[0], mt0), mn1 = fmaxf(mI[1], mt1);
        float al0 = __expf(mI[0] - mn0), al1 = __expf(mI[1] - mn1);
        mI[0] = mn0; mI[1] = mn1;

        float sum0 = 0.f, sum1 = 0.f;
        #pragma unroll
        for (int nt = 0; nt < 8; ++nt) {
            S[nt][0] = __expf(S[nt][0] - mn0); sum0 += S[nt][0];
            S[nt][1] = __expf(S[nt][1] - mn0); sum0 += S[nt][1];
            S[nt][2] = __expf(S[nt][2] - mn1); sum1 += S[nt][2];
            S[nt][3] = __expf(S[nt][3] - mn1); sum1 += S[nt][3];
        }
        sum0 += __shfl_xor_sync(0xffffffffu, sum0, 1);
        sum0 += __shfl_xor_sync(0xffffffffu, sum0, 2);
        sum1 += __shfl_xor_sync(0xffffffffu, sum1, 1);
        sum1 += __shfl_xor_sync(0xffffffffu, sum1, 2);
        lI[0] = lI[0] * al0 + sum0;
        lI[1] = lI[1] * al1 + sum1;
        #pragma unroll
        for (int dt = 0; dt < 8; ++dt) {
            O[dt][0] *= al0; O[dt][1] *= al0;
            O[dt][2] *= al1; O[dt][3] *= al1;
        }

        // ---- P fragments (C-frag -> A-frag identity), hi/lo split ----
        uint32_t phi[8][2], plo[8][2];
        #pragma unroll
        for (int nt = 0; nt < 8; ++nt) {
            float h0 = __bfloat162float(__float2bfloat16(S[nt][0]));
            float h1 = __bfloat162float(__float2bfloat16(S[nt][1]));
            float h2 = __bfloat162float(__float2bfloat16(S[nt][2]));
            float h3 = __bfloat162float(__float2bfloat16(S[nt][3]));
            phi[nt][0] = pack_bf16(h0, h1);
            phi[nt][1] = pack_bf16(h2, h3);
            plo[nt][0] = pack_bf16(S[nt][0] - h0, S[nt][1] - h1);
            plo[nt][1] = pack_bf16(S[nt][2] - h2, S[nt][3] - h3);
        }

        // ---- O += P V (V frags via ldmatrix.x4.trans) ----
        #pragma unroll
        for (int ks = 0; ks < 4; ++ks) {
            uint32_t aP[4] = {phi[2*ks][0], phi[2*ks][1], phi[2*ks+1][0], phi[2*ks+1][1]};
            uint32_t aL[4] = {plo[2*ks][0], plo[2*ks][1], plo[2*ks+1][0], plo[2*ks+1][1]};
            #pragma unroll
            for (int dp = 0; dp < 4; ++dp) {
                uint32_t vh[4], vl[4];
                const int wo = ks * 576 + vrow + dp * 8 + vd;
                ldsm4t(vh, vH + wo * 4);
                ldsm4t(vl, vL + wo * 4);
                mma16816(O[2*dp],     aP, vh);
                mma16816(O[2*dp],     aL, vh);
                mma16816(O[2*dp],     aP, vl);
                mma16816(O[2*dp + 1], aP, vh + 2);
                mma16816(O[2*dp + 1], aL, vh + 2);
                mma16816(O[2*dp + 1], aP, vl + 2);
            }
        }
    }

    // ---- epilogue ----
    const float inv0 = 1.0f / lI[0];
    const float inv1 = 1.0f / lI[1];
    const size_t row0 = (size_t)b * Tt + qt * 64 + w * 16 + g;
    const size_t row1 = row0 + 8;
    #pragma unroll
    for (int dt = 0; dt < 8; ++dt) {
        const int col = h * 64 + dt * 8 + 2 * t;
        float2 vr0 = *(const float2*)(vres + row0 * 512 + col);
        float2 vr1 = *(const float2*)(vres + row1 * 512 + col);
        float2 o0 = make_float2(O[dt][0] * inv0 + vr0.x, O[dt][1] * inv0 + vr0.y);
        float2 o1 = make_float2(O[dt][2] * inv1 + vr1.x, O[dt][3] * inv1 + vr1.y);
        *(float2*)(out + row0 * 512 + col) = o0;
        *(float2*)(out + row1 * 512 + col) = o1;
    }
}

// ---------------------------------------------------------------------------
extern "C" void kernel_launch(void* const* d_in, const int* in_sizes, int n_in,
                              void* d_out, int out_size)
{
    const float* x    = (const float*)d_in[0];
    const float* WDQ  = (const float*)d_in[1];
    const float* WUQ  = (const float*)d_in[2];
    const float* WQR  = (const float*)d_in[3];
    const float* WDKV = (const float*)d_in[4];
    const float* WUK  = (const float*)d_in[5];
    const float* WUV  = (const float*)d_in[6];
    const float* WKR  = (const float*)d_in[7];
    const float* WVR  = (const float*)d_in[8];
    const float* WO   = (const float*)d_in[9];
    const float* qlnw = (const float*)d_in[10];
    const float* kvlnw= (const float*)d_in[11];
    const float* qhw  = (const float*)d_in[12];
    const float* khw  = (const float*)d_in[13];
    float* out = (float*)d_out;

    float *cq, *qn, *qr, *ckv, *kn, *kr, *vraw, *vres, *q, *ao;
    __nv_bfloat16 *khi, *klo, *vhi, *vlo, *ahi, *alo, *whi, *wlo;
    cudaGetSymbolAddress((void**)&cq,   g_cq);
    cudaGetSymbolAddress((void**)&qn,   g_qn);
    cudaGetSymbolAddress((void**)&qr,   g_qr);
    cudaGetSymbolAddress((void**)&ckv,  g_ckv);
    cudaGetSymbolAddress((void**)&kn,   g_kn);
    cudaGetSymbolAddress((void**)&kr,   g_kr);
    cudaGetSymbolAddress((void**)&vraw, g_vraw);
    cudaGetSymbolAddress((void**)&vres, g_vres);
    cudaGetSymbolAddress((void**)&q,    g_q);
    cudaGetSymbolAddress((void**)&ao,   g_ao);
    cudaGetSymbolAddress((void**)&khi,  g_khi);
    cudaGetSymbolAddress((void**)&klo,  g_klo);
    cudaGetSymbolAddress((void**)&vhi,  g_vhi);
    cudaGetSymbolAddress((void**)&vlo,  g_vlo);
    cudaGetSymbolAddress((void**)&ahi,  g_ahi);
    cudaGetSymbolAddress((void**)&alo,  g_alo);
    cudaGetSymbolAddress((void**)&whi,  g_whi);
    cudaGetSymbolAddress((void**)&wlo,  g_wlo);

    // ---- weights: one batched transpose+split launch ----
    {
        TJobs jb;
        const float* Ws[9] = {WDQ, WUQ, WQR, WDKV, WUK, WUV, WKR, WVR, WO};
        const int Ks[9]    = {512, 256, 256, 512, 128, 128, 512, 512, 512};
        const int Ns[9]    = {256, 256, 256, 128, 64,  128, 64,  512, 512};
        const int Os[9]    = {OFF_DQ, OFF_UQ, OFF_QR, OFF_DKV, OFF_UK,
                              OFF_UV, OFF_KR, OFF_VR, OFF_WO};
        int acc = 0;
        for (int i = 0; i < 9; ++i) {
            jb.W[i] = Ws[i]; jb.K[i] = Ks[i]; jb.N[i] = Ns[i]; jb.woff[i] = Os[i];
            jb.t0[i] = acc;
            acc += (Ks[i] / 32) * (Ns[i] / 32);
        }
        jb.t0[9] = acc;   // 888
        transpose_split_all<<<acc, dim3(32, 8)>>>(jb, whi, wlo);
    }

    // ---- x-split, then all GEMMs that consume x ----
    split_act<<<BT*512/1024, 256>>>(x, ahi, alo);
    hgemm<128><<<dim3(2, 64), 256>>>(ahi, alo, whi + OFF_DQ,  wlo + OFF_DQ,  cq,   BT, 256, 512);
    hgemm<128><<<dim3(1, 64), 256>>>(ahi, alo, whi + OFF_DKV, wlo + OFF_DKV, ckv,  BT, 128, 512);
    hgemm<64> <<<dim3(1, 64), 256>>>(ahi, alo, whi + OFF_KR,  wlo + OFF_KR,  kr,   BT, 64,  512);
    hgemm<128><<<dim3(4, 64), 256>>>(ahi, alo, whi + OFF_VR,  wlo + OFF_VR,  vres, BT, 512, 512);

    // ---- Q path ----
    rms_inplace<<<BT, 128>>>(cq, qlnw, 256);
    split_act<<<BT*256/1024, 256>>>(cq, ahi, alo);
    hgemm<128><<<dim3(2, 64), 256>>>(ahi, alo, whi + OFF_UQ, wlo + OFF_UQ, qn, BT, 256, 256);
    hgemm<128><<<dim3(2, 64), 256>>>(ahi, alo, whi + OFF_QR, wlo + OFF_QR, qr, BT, 256, 256);

    // ---- KV path ----
    rms_inplace<<<BT, 128>>>(ckv, kvlnw, 128);
    split_act<<<BT*128/1024, 256>>>(ckv, ahi, alo);
    hgemm<64> <<<dim3(1, 64), 256>>>(ahi, alo, whi + OFF_UK, wlo + OFF_UK, kn,   BT, 64,  128);
    hgemm<128><<<dim3(1, 64), 256>>>(ahi, alo, whi + OFF_UV, wlo + OFF_UV, vraw, BT, 128, 128);

    // ---- rope + head-norm + layout ----
    assemble<<<dim3(Tt, Bb), 256>>>(qn, qr, kn, kr, vraw, qhw, khw,
                                    q, khi, klo, vhi, vlo);
    // ---- causal flash attention (+ residual add) ----
    flash_mma<<<dim3(Tt/64, Hh, Bb), 128>>>(q, khi, klo, vhi, vlo, vres, ao);
    // ---- output projection ----
    split_act<<<BT*512/1024, 256>>>(ao, ahi, alo);
    hgemm<128><<<dim3(4, 64), 256>>>(ahi, alo, whi + OFF_WO, wlo + OFF_WO, out, BT, 512, 512);
}